// round 7
// baseline (speedup 1.0000x reference)
#include <cuda_runtime.h>
#include <mma.h>
using namespace nvcuda;

#define BB   4
#define NN   1024
#define DDIM 512
#define HH   8
#define DHH  64
#define LLAY 6
#define DFFN 2048
#define MROWS (BB*NN)
#define NEGINF (-1000000000.0f)
#define CAP  512

// ---------------- scratch (static device memory; no allocs) ----------------
__device__ float buf_h [MROWS*DDIM];
__device__ float buf_q [MROWS*DDIM];
__device__ float buf_k [MROWS*DDIM];
__device__ float buf_v [MROWS*DDIM];
__device__ float buf_o [MROWS*DDIM];
__device__ float buf_x [MROWS*DDIM];
__device__ float buf_ff[MROWS*DFFN];
__device__ int   buf_nbr[(size_t)MROWS*CAP];
__device__ int   buf_cnt[MROWS];

// ---------------- LayerNorm ----------------
__global__ __launch_bounds__(256) void ln_kernel(const float* __restrict__ X,
                                                 const float* __restrict__ gam,
                                                 const float* __restrict__ bet,
                                                 float* __restrict__ Y)
{
    int row = blockIdx.x;
    const float* x = X + (size_t)row * DDIM;
    int tid = threadIdx.x;
    float v0 = x[tid], v1 = x[tid + 256];

    __shared__ float red[8];
    __shared__ float stat[2];

    float s = v0 + v1;
    #pragma unroll
    for (int off = 16; off; off >>= 1) s += __shfl_xor_sync(0xffffffffu, s, off);
    if ((tid & 31) == 0) red[tid >> 5] = s;
    __syncthreads();
    if (tid < 8) {
        float t = red[tid];
        #pragma unroll
        for (int off = 4; off; off >>= 1) t += __shfl_xor_sync(0xffu, t, off);
        if (tid == 0) stat[0] = t * (1.0f / DDIM);
    }
    __syncthreads();
    float mean = stat[0];
    float d0 = v0 - mean, d1 = v1 - mean;
    float q = d0*d0 + d1*d1;
    #pragma unroll
    for (int off = 16; off; off >>= 1) q += __shfl_xor_sync(0xffffffffu, q, off);
    if ((tid & 31) == 0) red[tid >> 5] = q;
    __syncthreads();
    if (tid < 8) {
        float t = red[tid];
        #pragma unroll
        for (int off = 4; off; off >>= 1) t += __shfl_xor_sync(0xffu, t, off);
        if (tid == 0) stat[1] = rsqrtf(t * (1.0f / DDIM) + 1e-5f);
    }
    __syncthreads();
    float rs = stat[1];
    Y[(size_t)row*DDIM + tid]       = d0 * rs * gam[tid]       + bet[tid];
    Y[(size_t)row*DDIM + tid + 256] = d1 * rs * gam[tid + 256] + bet[tid + 256];
}

// ---------------- neighbor-list builder (one warp per query) ----------------
__global__ __launch_bounds__(256) void nbr_build_kernel(const float* __restrict__ xy,
                                                        const int* __restrict__ alive,
                                                        const int* __restrict__ species,
                                                        int* __restrict__ nbr,
                                                        int* __restrict__ cnt)
{
    int b = blockIdx.y;
    int q = blockIdx.x * 8 + (threadIdx.x >> 5);
    int lane = threadIdx.x & 31;
    float xq = xy[(b*NN+q)*2], yq = xy[(b*NN+q)*2+1];
    int sq = species[b*NN+q];
    bool qa = sq < 2, qp = sq == 2;
    size_t base = (size_t)(b*NN + q) * CAP;
    int c = 0;
    for (int k0 = 0; k0 < NN; k0 += 32) {
        int k = k0 + lane;
        float xk = xy[(b*NN+k)*2], yk = xy[(b*NN+k)*2+1];
        bool un = alive[b*NN+k] != 0;
        float dx = __fadd_rn(xq, -xk), dy = __fadd_rn(yq, -yk);
        float d2 = __fadd_rn(__fmul_rn(dx,dx), __fmul_rn(dy,dy));
        if (d2 > 100.0f) un = false;
        int sk = species[b*NN+k];
        bool ka = sk < 2, kp = sk == 2;
        if ((qa && kp) || (qp && ka)) un = false;
        unsigned bal = __ballot_sync(0xffffffffu, un);
        int pos = c + __popc(bal & ((1u << lane) - 1u));
        if (un && pos < CAP) nbr[base + pos] = k;
        c += __popc(bal);
    }
    if (lane == 0) cnt[b*NN + q] = (c > CAP) ? CAP : c;
}

// ---------------- sparse gather attention: one warp per (b,h,query) ----------------
__global__ __launch_bounds__(256) void attn_sparse_kernel(const float* __restrict__ Q,
                                                          const float* __restrict__ Kg,
                                                          const float* __restrict__ Vg,
                                                          const int* __restrict__ nbr,
                                                          const int* __restrict__ cnt,
                                                          float* __restrict__ O)
{
    int b = blockIdx.z, h = blockIdx.y;
    int w = threadIdx.x >> 5, lane = threadIdx.x & 31;
    int q = blockIdx.x * 8 + w;

    __shared__ float Qs[8][DHH];
    __shared__ int   nbs[8][CAP];
    __shared__ float sc[8][CAP];

    size_t qrow = (size_t)(b*NN + q);
    int c = cnt[qrow];

    // Q row into smem (2 floats per lane)
    Qs[w][lane]      = Q[qrow*DDIM + h*DHH + lane];
    Qs[w][lane + 32] = Q[qrow*DDIM + h*DHH + lane + 32];
    // neighbor indices
    for (int i = lane; i < c; i += 32) nbs[w][i] = nbr[qrow*CAP + i];
    __syncwarp();

    // phase 1: scores
    float mloc = -3.0e38f;
    for (int i = lane; i < c; i += 32) {
        int idx = nbs[w][i];
        const float4* kp = reinterpret_cast<const float4*>(&Kg[((size_t)(b*NN+idx))*DDIM + h*DHH]);
        float s = 0.f;
        #pragma unroll
        for (int d4 = 0; d4 < 16; d4++) {
            float4 kv = kp[d4];
            s += Qs[w][d4*4+0]*kv.x + Qs[w][d4*4+1]*kv.y
               + Qs[w][d4*4+2]*kv.z + Qs[w][d4*4+3]*kv.w;
        }
        s *= 0.125f;
        sc[w][i] = s;
        mloc = fmaxf(mloc, s);
    }
    #pragma unroll
    for (int off = 16; off; off >>= 1) mloc = fmaxf(mloc, __shfl_xor_sync(0xffffffffu, mloc, off));

    // phase 2: exp + sum
    float lsum = 0.f;
    for (int i = lane; i < c; i += 32) {
        float p = expf(sc[w][i] - mloc);
        sc[w][i] = p;
        lsum += p;
    }
    #pragma unroll
    for (int off = 16; off; off >>= 1) lsum += __shfl_xor_sync(0xffffffffu, lsum, off);
    __syncwarp();

    // phase 3: weighted V gather (lane owns dims lane, lane+32)
    float o0 = 0.f, o1 = 0.f;
    int j = 0;
    for (; j + 2 <= c; j += 2) {
        float w0 = sc[w][j], w1 = sc[w][j+1];
        int i0 = nbs[w][j], i1 = nbs[w][j+1];
        const float* v0p = &Vg[((size_t)(b*NN+i0))*DDIM + h*DHH];
        const float* v1p = &Vg[((size_t)(b*NN+i1))*DDIM + h*DHH];
        float a0 = v0p[lane], a1 = v0p[lane+32];
        float b0 = v1p[lane], b1 = v1p[lane+32];
        o0 += w0*a0 + w1*b0;
        o1 += w0*a1 + w1*b1;
    }
    for (; j < c; j++) {
        float wj = sc[w][j];
        const float* vp = &Vg[((size_t)(b*NN+nbs[w][j]))*DDIM + h*DHH];
        o0 += wj*vp[lane];
        o1 += wj*vp[lane+32];
    }

    float inv = (c > 0) ? 1.0f / lsum : 0.f;
    O[qrow*DDIM + h*DHH + lane]      = o0 * inv;
    O[qrow*DDIM + h*DHH + lane + 32] = o1 * inv;
}

// ---------------- dense fallback for zero-neighbor rows (exact reference path) ----------------
__global__ __launch_bounds__(256) void attn_dense_fallback(const float* __restrict__ Q,
                                                           const float* __restrict__ Kg,
                                                           const float* __restrict__ Vg,
                                                           const float* __restrict__ xy,
                                                           const int* __restrict__ alive,
                                                           const int* __restrict__ species,
                                                           const int* __restrict__ cnt,
                                                           float* __restrict__ O)
{
    int b = blockIdx.y, q = blockIdx.x;
    if (cnt[b*NN + q] != 0) return;

    int tid = threadIdx.x;
    __shared__ float sc[NN];
    __shared__ float qs[DHH];
    __shared__ float red[8];
    __shared__ float stat[2];

    float xq = xy[(b*NN+q)*2], yq = xy[(b*NN+q)*2+1];
    int sq = species[b*NN+q];
    bool qa = sq < 2, qp = sq == 2;

    for (int h = 0; h < HH; h++) {
        if (tid < DHH) qs[tid] = Q[((size_t)(b*NN+q))*DDIM + h*DHH + tid];
        __syncthreads();

        float mloc = -3.0e38f;
        for (int k = tid; k < NN; k += 256) {
            float xk = xy[(b*NN+k)*2], yk = xy[(b*NN+k)*2+1];
            float bias = (alive[b*NN+k] == 0) ? NEGINF : 0.f;
            float dx = __fadd_rn(xq, -xk), dy = __fadd_rn(yq, -yk);
            float d2 = __fadd_rn(__fmul_rn(dx,dx), __fmul_rn(dy,dy));
            if (d2 > 100.0f) bias += NEGINF;
            int sk = species[b*NN+k];
            bool ka = sk < 2, kp = sk == 2;
            if ((qa && kp) || (qp && ka)) bias += NEGINF;
            const float* kp2 = &Kg[((size_t)(b*NN+k))*DDIM + h*DHH];
            float s = 0.f;
            for (int d = 0; d < DHH; d++) s += qs[d] * kp2[d];
            s = s * 0.125f + bias;
            sc[k] = s;
            mloc = fmaxf(mloc, s);
        }
        // block max
        #pragma unroll
        for (int off = 16; off; off >>= 1) mloc = fmaxf(mloc, __shfl_xor_sync(0xffffffffu, mloc, off));
        if ((tid & 31) == 0) red[tid >> 5] = mloc;
        __syncthreads();
        if (tid < 8) {
            float t = red[tid];
            #pragma unroll
            for (int off = 4; off; off >>= 1) t = fmaxf(t, __shfl_xor_sync(0xffu, t, off));
            if (tid == 0) stat[0] = t;
        }
        __syncthreads();
        float m = stat[0];
        float ls = 0.f;
        for (int k = tid; k < NN; k += 256) {
            float p = expf(sc[k] - m);
            sc[k] = p;
            ls += p;
        }
        #pragma unroll
        for (int off = 16; off; off >>= 1) ls += __shfl_xor_sync(0xffffffffu, ls, off);
        if ((tid & 31) == 0) red[tid >> 5] = ls;
        __syncthreads();
        if (tid < 8) {
            float t = red[tid];
            #pragma unroll
            for (int off = 4; off; off >>= 1) t += __shfl_xor_sync(0xffu, t, off);
            if (tid == 0) stat[1] = t;
        }
        __syncthreads();
        float inv = 1.0f / stat[1];

        if (tid < DHH) {
            float acc = 0.f;
            for (int k = 0; k < NN; k++)
                acc += sc[k] * Vg[((size_t)(b*NN+k))*DDIM + h*DHH + tid];
            O[((size_t)(b*NN+q))*DDIM + h*DHH + tid] = acc * inv;
        }
        __syncthreads();
    }
}

// ---------------- tf32 tensor-core GEMM: BM=128, BN=128, BK=32, double-buffered ----------------
#define GBM 128
#define GBN 128
#define GBK 32
#define ALD 36
#define BLD 136
#define GEMM_SMEM_BYTES ((2*GBM*ALD + 2*GBK*BLD + 8*256) * 4)

__device__ __forceinline__ float gelu_exact(float x) {
    return 0.5f * x * (1.0f + erff(x * 0.70710678118654752440f));
}

__global__ __launch_bounds__(256) void gemm_tc(const float* __restrict__ A,
                                               const float* __restrict__ W,
                                               const float* __restrict__ bias,
                                               const float* __restrict__ resid,
                                               float* __restrict__ C,
                                               int M, int K, int Nc, int act)
{
    extern __shared__ float smem[];
    float* As    = smem;                           // 2 x 128 x 36
    float* Bs    = smem + 2*GBM*ALD;               // 2 x 32 x 136
    float* stage = smem + 2*GBM*ALD + 2*GBK*BLD;   // 8 x 256

    int tid  = threadIdx.x;
    int warp = tid >> 5;
    int lane = tid & 31;
    int row0 = blockIdx.y * GBM;
    int col0 = blockIdx.x * GBN;
    int wm = warp >> 1;          // 0..3
    int wn = warp & 1;           // 0..1

    // loader coordinates
    int ar[4], ac[4], br[4], bc[4];
    #pragma unroll
    for (int it = 0; it < 4; it++) {
        int f = it * 256 + tid;
        ar[it] = f >> 3;  ac[it] = (f & 7) * 4;
        br[it] = f >> 5;  bc[it] = (f & 31) * 4;
    }

    wmma::fragment<wmma::accumulator, 16,16,8, float> acc[2][4];
    #pragma unroll
    for (int mi = 0; mi < 2; mi++)
        #pragma unroll
        for (int ni = 0; ni < 4; ni++) wmma::fill_fragment(acc[mi][ni], 0.f);

    // prologue: tile 0 direct to buffer 0
    #pragma unroll
    for (int it = 0; it < 4; it++) {
        float4 v = *reinterpret_cast<const float4*>(&A[(size_t)(row0 + ar[it]) * K + ac[it]]);
        float* d = &As[ar[it] * ALD + ac[it]];
        d[0] = wmma::__float_to_tf32(v.x); d[1] = wmma::__float_to_tf32(v.y);
        d[2] = wmma::__float_to_tf32(v.z); d[3] = wmma::__float_to_tf32(v.w);
        float4 u = *reinterpret_cast<const float4*>(&W[(size_t)br[it] * Nc + col0 + bc[it]]);
        float* e = &Bs[br[it] * BLD + bc[it]];
        e[0] = wmma::__float_to_tf32(u.x); e[1] = wmma::__float_to_tf32(u.y);
        e[2] = wmma::__float_to_tf32(u.z); e[3] = wmma::__float_to_tf32(u.w);
    }
    __syncthreads();

    int niter = K / GBK;
    for (int kt = 0; kt < niter; kt++) {
        int cur = kt & 1;
        float4 ra[4], rb[4];
        bool more = (kt + 1 < niter);
        if (more) {
            int k0 = (kt + 1) * GBK;
            #pragma unroll
            for (int it = 0; it < 4; it++) {
                ra[it] = *reinterpret_cast<const float4*>(&A[(size_t)(row0 + ar[it]) * K + k0 + ac[it]]);
                rb[it] = *reinterpret_cast<const float4*>(&W[(size_t)(k0 + br[it]) * Nc + col0 + bc[it]]);
            }
        }

        const float* Ac = As + cur * GBM * ALD;
        const float* Bc = Bs + cur * GBK * BLD;
        #pragma unroll
        for (int kk = 0; kk < GBK; kk += 8) {
            wmma::fragment<wmma::matrix_a, 16,16,8, wmma::precision::tf32, wmma::row_major> af[2];
            wmma::fragment<wmma::matrix_b, 16,16,8, wmma::precision::tf32, wmma::row_major> bf[4];
            #pragma unroll
            for (int mi = 0; mi < 2; mi++)
                wmma::load_matrix_sync(af[mi], &Ac[(wm*32 + mi*16) * ALD + kk], ALD);
            #pragma unroll
            for (int ni = 0; ni < 4; ni++)
                wmma::load_matrix_sync(bf[ni], &Bc[kk * BLD + wn*64 + ni*16], BLD);
            #pragma unroll
            for (int mi = 0; mi < 2; mi++)
                #pragma unroll
                for (int ni = 0; ni < 4; ni++)
                    wmma::mma_sync(acc[mi][ni], af[mi], bf[ni], acc[mi][ni]);
        }

        if (more) {
            int nxt = cur ^ 1;
            float* An = As + nxt * GBM * ALD;
            float* Bn = Bs + nxt * GBK * BLD;
            #pragma unroll
            for (int it = 0; it < 4; it++) {
                float* d = &An[ar[it] * ALD + ac[it]];
                d[0] = wmma::__float_to_tf32(ra[it].x); d[1] = wmma::__float_to_tf32(ra[it].y);
                d[2] = wmma::__float_to_tf32(ra[it].z); d[3] = wmma::__float_to_tf32(ra[it].w);
                float* e = &Bn[br[it] * BLD + bc[it]];
                e[0] = wmma::__float_to_tf32(rb[it].x); e[1] = wmma::__float_to_tf32(rb[it].y);
                e[2] = wmma::__float_to_tf32(rb[it].z); e[3] = wmma::__float_to_tf32(rb[it].w);
            }
        }
        __syncthreads();
    }

    // epilogue via per-warp staging tile
    float* st = &stage[warp * 256];
    #pragma unroll
    for (int mi = 0; mi < 2; mi++) {
        #pragma unroll
        for (int ni = 0; ni < 4; ni++) {
            wmma::store_matrix_sync(st, acc[mi][ni], 16, wmma::mem_row_major);
            __syncwarp();
            int gr0 = row0 + wm*32 + mi*16;
            int gc0 = col0 + wn*64 + ni*16;
            #pragma unroll
            for (int i = 0; i < 8; i++) {
                int idx = i*32 + lane;
                int r = idx >> 4, cc = idx & 15;
                float v = st[idx];
                if (bias)  v += bias[gc0 + cc];
                if (act)   v  = gelu_exact(v);
                if (resid) v += resid[(size_t)(gr0 + r) * Nc + gc0 + cc];
                C[(size_t)(gr0 + r) * Nc + gc0 + cc] = v;
            }
            __syncwarp();
        }
    }
}

// ---------------- host orchestration ----------------
extern "C" void kernel_launch(void* const* d_in, const int* in_sizes, int n_in,
                              void* d_out, int out_size)
{
    (void)in_sizes; (void)n_in; (void)out_size;
    const float* tokens  = (const float*)d_in[0];
    const float* xy      = (const float*)d_in[1];
    const float* Wq      = (const float*)d_in[2];
    const float* Wk      = (const float*)d_in[3];
    const float* Wv      = (const float*)d_in[4];
    const float* Wo      = (const float*)d_in[5];
    const float* bo      = (const float*)d_in[6];
    const float* W1      = (const float*)d_in[7];
    const float* b1      = (const float*)d_in[8];
    const float* W2      = (const float*)d_in[9];
    const float* b2      = (const float*)d_in[10];
    const float* g1      = (const float*)d_in[11];
    const float* be1     = (const float*)d_in[12];
    const float* g2      = (const float*)d_in[13];
    const float* be2     = (const float*)d_in[14];
    const float* gf      = (const float*)d_in[15];
    const float* bf      = (const float*)d_in[16];
    const int*   alive   = (const int*)d_in[17];
    const int*   species = (const int*)d_in[18];

    float *p_h, *p_q, *p_k, *p_v, *p_o, *p_x, *p_ff;
    int *p_nbr, *p_cnt;
    cudaGetSymbolAddress((void**)&p_h,  buf_h);
    cudaGetSymbolAddress((void**)&p_q,  buf_q);
    cudaGetSymbolAddress((void**)&p_k,  buf_k);
    cudaGetSymbolAddress((void**)&p_v,  buf_v);
    cudaGetSymbolAddress((void**)&p_o,  buf_o);
    cudaGetSymbolAddress((void**)&p_x,  buf_x);
    cudaGetSymbolAddress((void**)&p_ff, buf_ff);
    cudaGetSymbolAddress((void**)&p_nbr, buf_nbr);
    cudaGetSymbolAddress((void**)&p_cnt, buf_cnt);

    cudaFuncSetAttribute(gemm_tc, cudaFuncAttributeMaxDynamicSharedMemorySize, GEMM_SMEM_BYTES);

    const int M = MROWS;
    dim3 gD(DDIM / GBN, M / GBM);    // (4, 32)
    dim3 gF(DFFN / GBN, M / GBM);    // (16, 32)
    dim3 attnG(NN / 8, HH, BB);      // (128, 8, 4)
    dim3 fbG(NN, BB);

    nbr_build_kernel<<<dim3(NN/8, BB), 256>>>(xy, alive, species, p_nbr, p_cnt);

    for (int l = 0; l < LLAY; l++) {
        const float* xsrc = (l == 0) ? tokens : p_x;
        const float* Wq_l = Wq + (size_t)l * DDIM * DDIM;
        const float* Wk_l = Wk + (size_t)l * DDIM * DDIM;
        const float* Wv_l = Wv + (size_t)l * DDIM * DDIM;
        const float* Wo_l = Wo + (size_t)l * DDIM * DDIM;
        const float* W1_l = W1 + (size_t)l * DDIM * DFFN;
        const float* W2_l = W2 + (size_t)l * DFFN * DDIM;

        ln_kernel<<<M, 256>>>(xsrc, g1 + l * DDIM, be1 + l * DDIM, p_h);

        gemm_tc<<<gD, 256, GEMM_SMEM_BYTES>>>(p_h, Wq_l, nullptr, nullptr, p_q, M, DDIM, DDIM, 0);
        gemm_tc<<<gD, 256, GEMM_SMEM_BYTES>>>(p_h, Wk_l, nullptr, nullptr, p_k, M, DDIM, DDIM, 0);
        gemm_tc<<<gD, 256, GEMM_SMEM_BYTES>>>(p_h, Wv_l, nullptr, nullptr, p_v, M, DDIM, DDIM, 0);

        attn_sparse_kernel<<<attnG, 256>>>(p_q, p_k, p_v, p_nbr, p_cnt, p_o);
        attn_dense_fallback<<<fbG, 256>>>(p_q, p_k, p_v, xy, alive, species, p_cnt, p_o);

        gemm_tc<<<gD, 256, GEMM_SMEM_BYTES>>>(p_o, Wo_l, bo + l * DDIM, xsrc, p_x, M, DDIM, DDIM, 0);

        ln_kernel<<<M, 256>>>(p_x, g2 + l * DDIM, be2 + l * DDIM, p_h);

        gemm_tc<<<gF, 256, GEMM_SMEM_BYTES>>>(p_h, W1_l, b1 + l * DFFN, nullptr, p_ff, M, DDIM, DFFN, 1);
        gemm_tc<<<gD, 256, GEMM_SMEM_BYTES>>>(p_ff, W2_l, b2 + l * DDIM, p_x, p_x, M, DFFN, DDIM, 0);
    }

    ln_kernel<<<M, 256>>>(p_x, gf, bf, (float*)d_out);
}

// round 8
// speedup vs baseline: 1.1010x; 1.1010x over previous
#include <cuda_runtime.h>
#include <mma.h>
using namespace nvcuda;

#define BB   4
#define NN   1024
#define DDIM 512
#define HH   8
#define DHH  64
#define LLAY 6
#define DFFN 2048
#define MROWS (BB*NN)
#define NEGINF (-1000000000.0f)
#define CAP  512

// ---------------- scratch (static device memory; no allocs) ----------------
__device__ float buf_h [MROWS*DDIM];
__device__ float buf_q [MROWS*DDIM];
__device__ float buf_k [MROWS*DDIM];
__device__ float buf_v [MROWS*DDIM];
__device__ float buf_o [MROWS*DDIM];
__device__ float buf_x [MROWS*DDIM];
__device__ float buf_ff[MROWS*DFFN];
__device__ int   buf_nbr[(size_t)MROWS*CAP];
__device__ int   buf_cnt[MROWS];

// ---------------- LayerNorm ----------------
__global__ __launch_bounds__(256) void ln_kernel(const float* __restrict__ X,
                                                 const float* __restrict__ gam,
                                                 const float* __restrict__ bet,
                                                 float* __restrict__ Y)
{
    int row = blockIdx.x;
    const float* x = X + (size_t)row * DDIM;
    int tid = threadIdx.x;
    float v0 = x[tid], v1 = x[tid + 256];

    __shared__ float red[8];
    __shared__ float stat[2];

    float s = v0 + v1;
    #pragma unroll
    for (int off = 16; off; off >>= 1) s += __shfl_xor_sync(0xffffffffu, s, off);
    if ((tid & 31) == 0) red[tid >> 5] = s;
    __syncthreads();
    if (tid < 8) {
        float t = red[tid];
        #pragma unroll
        for (int off = 4; off; off >>= 1) t += __shfl_xor_sync(0xffu, t, off);
        if (tid == 0) stat[0] = t * (1.0f / DDIM);
    }
    __syncthreads();
    float mean = stat[0];
    float d0 = v0 - mean, d1 = v1 - mean;
    float q = d0*d0 + d1*d1;
    #pragma unroll
    for (int off = 16; off; off >>= 1) q += __shfl_xor_sync(0xffffffffu, q, off);
    if ((tid & 31) == 0) red[tid >> 5] = q;
    __syncthreads();
    if (tid < 8) {
        float t = red[tid];
        #pragma unroll
        for (int off = 4; off; off >>= 1) t += __shfl_xor_sync(0xffu, t, off);
        if (tid == 0) stat[1] = rsqrtf(t * (1.0f / DDIM) + 1e-5f);
    }
    __syncthreads();
    float rs = stat[1];
    Y[(size_t)row*DDIM + tid]       = d0 * rs * gam[tid]       + bet[tid];
    Y[(size_t)row*DDIM + tid + 256] = d1 * rs * gam[tid + 256] + bet[tid + 256];
}

// ---------------- neighbor-list builder (one warp per query) ----------------
__global__ __launch_bounds__(256) void nbr_build_kernel(const float* __restrict__ xy,
                                                        const int* __restrict__ alive,
                                                        const int* __restrict__ species,
                                                        int* __restrict__ nbr,
                                                        int* __restrict__ cnt)
{
    int b = blockIdx.y;
    int q = blockIdx.x * 8 + (threadIdx.x >> 5);
    int lane = threadIdx.x & 31;
    float xq = xy[(b*NN+q)*2], yq = xy[(b*NN+q)*2+1];
    int sq = species[b*NN+q];
    bool qa = sq < 2, qp = sq == 2;
    size_t base = (size_t)(b*NN + q) * CAP;
    int c = 0;
    for (int k0 = 0; k0 < NN; k0 += 32) {
        int k = k0 + lane;
        float xk = xy[(b*NN+k)*2], yk = xy[(b*NN+k)*2+1];
        bool un = alive[b*NN+k] != 0;
        float dx = __fadd_rn(xq, -xk), dy = __fadd_rn(yq, -yk);
        float d2 = __fadd_rn(__fmul_rn(dx,dx), __fmul_rn(dy,dy));
        if (d2 > 100.0f) un = false;
        int sk = species[b*NN+k];
        bool ka = sk < 2, kp = sk == 2;
        if ((qa && kp) || (qp && ka)) un = false;
        unsigned bal = __ballot_sync(0xffffffffu, un);
        int pos = c + __popc(bal & ((1u << lane) - 1u));
        if (un && pos < CAP) nbr[base + pos] = k;
        c += __popc(bal);
    }
    if (lane == 0) cnt[b*NN + q] = (c > CAP) ? CAP : c;
}

// ---------------- sparse gather attention: one warp per (b,h,query) ----------------
__global__ __launch_bounds__(256) void attn_sparse_kernel(const float* __restrict__ Q,
                                                          const float* __restrict__ Kg,
                                                          const float* __restrict__ Vg,
                                                          const int* __restrict__ nbr,
                                                          const int* __restrict__ cnt,
                                                          float* __restrict__ O)
{
    int b = blockIdx.z, h = blockIdx.y;
    int w = threadIdx.x >> 5, lane = threadIdx.x & 31;
    int q = blockIdx.x * 8 + w;

    __shared__ float Qs[8][DHH];
    __shared__ int   nbs[8][CAP];
    __shared__ float sc[8][CAP];

    size_t qrow = (size_t)(b*NN + q);
    int c = cnt[qrow];

    Qs[w][lane]      = Q[qrow*DDIM + h*DHH + lane];
    Qs[w][lane + 32] = Q[qrow*DDIM + h*DHH + lane + 32];
    for (int i = lane; i < c; i += 32) nbs[w][i] = nbr[qrow*CAP + i];
    __syncwarp();

    // phase 1: scores
    float mloc = -3.0e38f;
    for (int i = lane; i < c; i += 32) {
        int idx = nbs[w][i];
        const float4* kp = reinterpret_cast<const float4*>(&Kg[((size_t)(b*NN+idx))*DDIM + h*DHH]);
        float s = 0.f;
        #pragma unroll
        for (int d4 = 0; d4 < 16; d4++) {
            float4 kv = kp[d4];
            s += Qs[w][d4*4+0]*kv.x + Qs[w][d4*4+1]*kv.y
               + Qs[w][d4*4+2]*kv.z + Qs[w][d4*4+3]*kv.w;
        }
        s *= 0.125f;
        sc[w][i] = s;
        mloc = fmaxf(mloc, s);
    }
    #pragma unroll
    for (int off = 16; off; off >>= 1) mloc = fmaxf(mloc, __shfl_xor_sync(0xffffffffu, mloc, off));

    // phase 2: exp + sum
    float lsum = 0.f;
    for (int i = lane; i < c; i += 32) {
        float p = expf(sc[w][i] - mloc);
        sc[w][i] = p;
        lsum += p;
    }
    #pragma unroll
    for (int off = 16; off; off >>= 1) lsum += __shfl_xor_sync(0xffffffffu, lsum, off);
    __syncwarp();

    // phase 3: weighted V gather
    float o0 = 0.f, o1 = 0.f;
    int j = 0;
    for (; j + 2 <= c; j += 2) {
        float w0 = sc[w][j], w1 = sc[w][j+1];
        int i0 = nbs[w][j], i1 = nbs[w][j+1];
        const float* v0p = &Vg[((size_t)(b*NN+i0))*DDIM + h*DHH];
        const float* v1p = &Vg[((size_t)(b*NN+i1))*DDIM + h*DHH];
        float a0 = v0p[lane], a1 = v0p[lane+32];
        float b0 = v1p[lane], b1 = v1p[lane+32];
        o0 += w0*a0 + w1*b0;
        o1 += w0*a1 + w1*b1;
    }
    for (; j < c; j++) {
        float wj = sc[w][j];
        const float* vp = &Vg[((size_t)(b*NN+nbs[w][j]))*DDIM + h*DHH];
        o0 += wj*vp[lane];
        o1 += wj*vp[lane+32];
    }

    float inv = (c > 0) ? 1.0f / lsum : 0.f;
    O[qrow*DDIM + h*DHH + lane]      = o0 * inv;
    O[qrow*DDIM + h*DHH + lane + 32] = o1 * inv;
}

// ---------------- dense fallback for zero-neighbor rows ----------------
__global__ __launch_bounds__(256) void attn_dense_fallback(const float* __restrict__ Q,
                                                           const float* __restrict__ Kg,
                                                           const float* __restrict__ Vg,
                                                           const float* __restrict__ xy,
                                                           const int* __restrict__ alive,
                                                           const int* __restrict__ species,
                                                           const int* __restrict__ cnt,
                                                           float* __restrict__ O)
{
    int b = blockIdx.y, q = blockIdx.x;
    if (cnt[b*NN + q] != 0) return;

    int tid = threadIdx.x;
    __shared__ float sc[NN];
    __shared__ float qs[DHH];
    __shared__ float red[8];
    __shared__ float stat[2];

    float xq = xy[(b*NN+q)*2], yq = xy[(b*NN+q)*2+1];
    int sq = species[b*NN+q];
    bool qa = sq < 2, qp = sq == 2;

    for (int h = 0; h < HH; h++) {
        if (tid < DHH) qs[tid] = Q[((size_t)(b*NN+q))*DDIM + h*DHH + tid];
        __syncthreads();

        float mloc = -3.0e38f;
        for (int k = tid; k < NN; k += 256) {
            float xk = xy[(b*NN+k)*2], yk = xy[(b*NN+k)*2+1];
            float bias = (alive[b*NN+k] == 0) ? NEGINF : 0.f;
            float dx = __fadd_rn(xq, -xk), dy = __fadd_rn(yq, -yk);
            float d2 = __fadd_rn(__fmul_rn(dx,dx), __fmul_rn(dy,dy));
            if (d2 > 100.0f) bias += NEGINF;
            int sk = species[b*NN+k];
            bool ka = sk < 2, kp = sk == 2;
            if ((qa && kp) || (qp && ka)) bias += NEGINF;
            const float* kp2 = &Kg[((size_t)(b*NN+k))*DDIM + h*DHH];
            float s = 0.f;
            for (int d = 0; d < DHH; d++) s += qs[d] * kp2[d];
            s = s * 0.125f + bias;
            sc[k] = s;
            mloc = fmaxf(mloc, s);
        }
        #pragma unroll
        for (int off = 16; off; off >>= 1) mloc = fmaxf(mloc, __shfl_xor_sync(0xffffffffu, mloc, off));
        if ((tid & 31) == 0) red[tid >> 5] = mloc;
        __syncthreads();
        if (tid < 8) {
            float t = red[tid];
            #pragma unroll
            for (int off = 4; off; off >>= 1) t = fmaxf(t, __shfl_xor_sync(0xffu, t, off));
            if (tid == 0) stat[0] = t;
        }
        __syncthreads();
        float m = stat[0];
        float ls = 0.f;
        for (int k = tid; k < NN; k += 256) {
            float p = expf(sc[k] - m);
            sc[k] = p;
            ls += p;
        }
        #pragma unroll
        for (int off = 16; off; off >>= 1) ls += __shfl_xor_sync(0xffffffffu, ls, off);
        if ((tid & 31) == 0) red[tid >> 5] = ls;
        __syncthreads();
        if (tid < 8) {
            float t = red[tid];
            #pragma unroll
            for (int off = 4; off; off >>= 1) t += __shfl_xor_sync(0xffu, t, off);
            if (tid == 0) stat[1] = t;
        }
        __syncthreads();
        float inv = 1.0f / stat[1];

        if (tid < DHH) {
            float acc = 0.f;
            for (int k = 0; k < NN; k++)
                acc += sc[k] * Vg[((size_t)(b*NN+k))*DDIM + h*DHH + tid];
            O[((size_t)(b*NN+q))*DDIM + h*DHH + tid] = acc * inv;
        }
        __syncthreads();
    }
}

// ---------------- tf32 GEMM core: BM=128 BN=64 BK=32, double-buffered, 2 CTAs/SM ----------------
#define GBM 128
#define GBN 64
#define GBK 32
#define ALD 36
#define BLD 72
#define GEMM_SMEM_FLOATS (2*GBM*ALD + 2*GBK*BLD)   // 13824 floats = 55296 B
#define GEMM_SMEM_BYTES (GEMM_SMEM_FLOATS * 4)

__device__ __forceinline__ float gelu_exact(float x) {
    return 0.5f * x * (1.0f + erff(x * 0.70710678118654752440f));
}

__device__ __forceinline__ void gemm_core(const float* __restrict__ A,
                                          const float* __restrict__ W,
                                          const float* __restrict__ bias,
                                          const float* __restrict__ resid,
                                          float* __restrict__ C,
                                          int K, int Nc, int act,
                                          int row0, int col0, float* smem)
{
    float* As = smem;                 // 2 x 128 x 36
    float* Bs = smem + 2*GBM*ALD;     // 2 x 32 x 72

    int tid  = threadIdx.x;
    int warp = tid >> 5;
    int lane = tid & 31;
    int wm = warp >> 1;
    int wn = warp & 1;

    // loader coords: A = 4 float4/thread, B = 2 float4/thread
    int ar[4], ac[4];
    #pragma unroll
    for (int it = 0; it < 4; it++) {
        int f = it * 256 + tid;
        ar[it] = f >> 3;  ac[it] = (f & 7) * 4;
    }
    int br0 = tid >> 4, bc0 = (tid & 15) * 4;
    int br1 = (256 + tid) >> 4, bc1 = bc0;

    wmma::fragment<wmma::accumulator, 16,16,8, float> acc[2][2];
    #pragma unroll
    for (int mi = 0; mi < 2; mi++)
        #pragma unroll
        for (int ni = 0; ni < 2; ni++) wmma::fill_fragment(acc[mi][ni], 0.f);

    // prologue
    #pragma unroll
    for (int it = 0; it < 4; it++) {
        float4 v = *reinterpret_cast<const float4*>(&A[(size_t)(row0 + ar[it]) * K + ac[it]]);
        float* d = &As[ar[it] * ALD + ac[it]];
        d[0] = wmma::__float_to_tf32(v.x); d[1] = wmma::__float_to_tf32(v.y);
        d[2] = wmma::__float_to_tf32(v.z); d[3] = wmma::__float_to_tf32(v.w);
    }
    {
        float4 u0 = *reinterpret_cast<const float4*>(&W[(size_t)br0 * Nc + col0 + bc0]);
        float4 u1 = *reinterpret_cast<const float4*>(&W[(size_t)br1 * Nc + col0 + bc1]);
        float* e0 = &Bs[br0 * BLD + bc0];
        e0[0] = wmma::__float_to_tf32(u0.x); e0[1] = wmma::__float_to_tf32(u0.y);
        e0[2] = wmma::__float_to_tf32(u0.z); e0[3] = wmma::__float_to_tf32(u0.w);
        float* e1 = &Bs[br1 * BLD + bc1];
        e1[0] = wmma::__float_to_tf32(u1.x); e1[1] = wmma::__float_to_tf32(u1.y);
        e1[2] = wmma::__float_to_tf32(u1.z); e1[3] = wmma::__float_to_tf32(u1.w);
    }
    __syncthreads();

    int niter = K / GBK;
    for (int kt = 0; kt < niter; kt++) {
        int cur = kt & 1;
        float4 ra[4], rb0, rb1;
        bool more = (kt + 1 < niter);
        if (more) {
            int k0 = (kt + 1) * GBK;
            #pragma unroll
            for (int it = 0; it < 4; it++)
                ra[it] = *reinterpret_cast<const float4*>(&A[(size_t)(row0 + ar[it]) * K + k0 + ac[it]]);
            rb0 = *reinterpret_cast<const float4*>(&W[(size_t)(k0 + br0) * Nc + col0 + bc0]);
            rb1 = *reinterpret_cast<const float4*>(&W[(size_t)(k0 + br1) * Nc + col0 + bc1]);
        }

        const float* Ac = As + cur * GBM * ALD;
        const float* Bc = Bs + cur * GBK * BLD;
        #pragma unroll
        for (int kk = 0; kk < GBK; kk += 8) {
            wmma::fragment<wmma::matrix_a, 16,16,8, wmma::precision::tf32, wmma::row_major> af[2];
            wmma::fragment<wmma::matrix_b, 16,16,8, wmma::precision::tf32, wmma::row_major> bf[2];
            #pragma unroll
            for (int mi = 0; mi < 2; mi++)
                wmma::load_matrix_sync(af[mi], &Ac[(wm*32 + mi*16) * ALD + kk], ALD);
            #pragma unroll
            for (int ni = 0; ni < 2; ni++)
                wmma::load_matrix_sync(bf[ni], &Bc[kk * BLD + wn*32 + ni*16], BLD);
            #pragma unroll
            for (int mi = 0; mi < 2; mi++)
                #pragma unroll
                for (int ni = 0; ni < 2; ni++)
                    wmma::mma_sync(acc[mi][ni], af[mi], bf[ni], acc[mi][ni]);
        }

        if (more) {
            int nxt = cur ^ 1;
            float* An = As + nxt * GBM * ALD;
            float* Bn = Bs + nxt * GBK * BLD;
            #pragma unroll
            for (int it = 0; it < 4; it++) {
                float* d = &An[ar[it] * ALD + ac[it]];
                d[0] = wmma::__float_to_tf32(ra[it].x); d[1] = wmma::__float_to_tf32(ra[it].y);
                d[2] = wmma::__float_to_tf32(ra[it].z); d[3] = wmma::__float_to_tf32(ra[it].w);
            }
            float* e0 = &Bn[br0 * BLD + bc0];
            e0[0] = wmma::__float_to_tf32(rb0.x); e0[1] = wmma::__float_to_tf32(rb0.y);
            e0[2] = wmma::__float_to_tf32(rb0.z); e0[3] = wmma::__float_to_tf32(rb0.w);
            float* e1 = &Bn[br1 * BLD + bc1];
            e1[0] = wmma::__float_to_tf32(rb1.x); e1[1] = wmma::__float_to_tf32(rb1.y);
            e1[2] = wmma::__float_to_tf32(rb1.z); e1[3] = wmma::__float_to_tf32(rb1.w);
        }
        __syncthreads();
    }

    // epilogue: stage aliases the As region (all mma reads completed at last sync)
    float* st = smem + warp * 256;
    #pragma unroll
    for (int mi = 0; mi < 2; mi++) {
        #pragma unroll
        for (int ni = 0; ni < 2; ni++) {
            wmma::store_matrix_sync(st, acc[mi][ni], 16, wmma::mem_row_major);
            __syncwarp();
            int gr0 = row0 + wm*32 + mi*16;
            int gc0 = col0 + wn*32 + ni*16;
            #pragma unroll
            for (int i = 0; i < 8; i++) {
                int idx = i*32 + lane;
                int r = idx >> 4, cc = idx & 15;
                float v = st[idx];
                if (bias)  v += bias[gc0 + cc];
                if (act)   v  = gelu_exact(v);
                if (resid) v += resid[(size_t)(gr0 + r) * Nc + gc0 + cc];
                C[(size_t)(gr0 + r) * Nc + gc0 + cc] = v;
            }
            __syncwarp();
        }
    }
}

__global__ __launch_bounds__(256, 2) void gemm_tc(const float* __restrict__ A,
                                                  const float* __restrict__ W,
                                                  const float* __restrict__ bias,
                                                  const float* __restrict__ resid,
                                                  float* __restrict__ C,
                                                  int K, int Nc, int act)
{
    extern __shared__ float smem[];
    gemm_core(A, W, bias, resid, C, K, Nc, act,
              blockIdx.y * GBM, blockIdx.x * GBN, smem);
}

__global__ __launch_bounds__(256, 2) void gemm_qkv(const float* __restrict__ A,
                                                   const float* __restrict__ Wq,
                                                   const float* __restrict__ Wk,
                                                   const float* __restrict__ Wv,
                                                   float* __restrict__ Cq,
                                                   float* __restrict__ Ck,
                                                   float* __restrict__ Cv)
{
    extern __shared__ float smem[];
    int z = blockIdx.z;
    const float* W = (z == 0) ? Wq : (z == 1) ? Wk : Wv;
    float*       C = (z == 0) ? Cq : (z == 1) ? Ck : Cv;
    gemm_core(A, W, nullptr, nullptr, C, DDIM, DDIM, 0,
              blockIdx.y * GBM, blockIdx.x * GBN, smem);
}

// ---------------- host orchestration ----------------
extern "C" void kernel_launch(void* const* d_in, const int* in_sizes, int n_in,
                              void* d_out, int out_size)
{
    (void)in_sizes; (void)n_in; (void)out_size;
    const float* tokens  = (const float*)d_in[0];
    const float* xy      = (const float*)d_in[1];
    const float* Wq      = (const float*)d_in[2];
    const float* Wk      = (const float*)d_in[3];
    const float* Wv      = (const float*)d_in[4];
    const float* Wo      = (const float*)d_in[5];
    const float* bo      = (const float*)d_in[6];
    const float* W1      = (const float*)d_in[7];
    const float* b1      = (const float*)d_in[8];
    const float* W2      = (const float*)d_in[9];
    const float* b2      = (const float*)d_in[10];
    const float* g1      = (const float*)d_in[11];
    const float* be1     = (const float*)d_in[12];
    const float* g2      = (const float*)d_in[13];
    const float* be2     = (const float*)d_in[14];
    const float* gf      = (const float*)d_in[15];
    const float* bf      = (const float*)d_in[16];
    const int*   alive   = (const int*)d_in[17];
    const int*   species = (const int*)d_in[18];

    float *p_h, *p_q, *p_k, *p_v, *p_o, *p_x, *p_ff;
    int *p_nbr, *p_cnt;
    cudaGetSymbolAddress((void**)&p_h,  buf_h);
    cudaGetSymbolAddress((void**)&p_q,  buf_q);
    cudaGetSymbolAddress((void**)&p_k,  buf_k);
    cudaGetSymbolAddress((void**)&p_v,  buf_v);
    cudaGetSymbolAddress((void**)&p_o,  buf_o);
    cudaGetSymbolAddress((void**)&p_x,  buf_x);
    cudaGetSymbolAddress((void**)&p_ff, buf_ff);
    cudaGetSymbolAddress((void**)&p_nbr, buf_nbr);
    cudaGetSymbolAddress((void**)&p_cnt, buf_cnt);

    static int smem_set = 0;
    if (!smem_set) {
        cudaFuncSetAttribute(gemm_tc,  cudaFuncAttributeMaxDynamicSharedMemorySize, GEMM_SMEM_BYTES);
        cudaFuncSetAttribute(gemm_qkv, cudaFuncAttributeMaxDynamicSharedMemorySize, GEMM_SMEM_BYTES);
        smem_set = 1;
    }

    const int M = MROWS;
    dim3 gD(DDIM / GBN, M / GBM);        // (8, 32) = 256
    dim3 gQKV(DDIM / GBN, M / GBM, 3);   // 768
    dim3 gF(DFFN / GBN, M / GBM);        // (32, 32) = 1024
    dim3 attnG(NN / 8, HH, BB);
    dim3 fbG(NN, BB);

    nbr_build_kernel<<<dim3(NN/8, BB), 256>>>(xy, alive, species, p_nbr, p_cnt);

    for (int l = 0; l < LLAY; l++) {
        const float* xsrc = (l == 0) ? tokens : p_x;
        const float* Wq_l = Wq + (size_t)l * DDIM * DDIM;
        const float* Wk_l = Wk + (size_t)l * DDIM * DDIM;
        const float* Wv_l = Wv + (size_t)l * DDIM * DDIM;
        const float* Wo_l = Wo + (size_t)l * DDIM * DDIM;
        const float* W1_l = W1 + (size_t)l * DDIM * DFFN;
        const float* W2_l = W2 + (size_t)l * DFFN * DDIM;

        ln_kernel<<<M, 256>>>(xsrc, g1 + l * DDIM, be1 + l * DDIM, p_h);

        gemm_qkv<<<gQKV, 256, GEMM_SMEM_BYTES>>>(p_h, Wq_l, Wk_l, Wv_l, p_q, p_k, p_v);

        attn_sparse_kernel<<<attnG, 256>>>(p_q, p_k, p_v, p_nbr, p_cnt, p_o);
        attn_dense_fallback<<<fbG, 256>>>(p_q, p_k, p_v, xy, alive, species, p_cnt, p_o);

        gemm_tc<<<gD, 256, GEMM_SMEM_BYTES>>>(p_o, Wo_l, bo + l * DDIM, xsrc, p_x, DDIM, DDIM, 0);

        ln_kernel<<<M, 256>>>(p_x, g2 + l * DDIM, be2 + l * DDIM, p_h);

        gemm_tc<<<gF, 256, GEMM_SMEM_BYTES>>>(p_h, W1_l, b1 + l * DFFN, nullptr, p_ff, DDIM, DFFN, 1);
        gemm_tc<<<gD, 256, GEMM_SMEM_BYTES>>>(p_ff, W2_l, b2 + l * DDIM, p_x, p_x, DFFN, DDIM, 0);
    }

    ln_kernel<<<M, 256>>>(p_x, gf, bf, (float*)d_out);
}

// round 10
// speedup vs baseline: 1.2096x; 1.0987x over previous
#include <cuda_runtime.h>
#include <mma.h>
using namespace nvcuda;

#define BB   4
#define NN   1024
#define DDIM 512
#define HH   8
#define DHH  64
#define LLAY 6
#define DFFN 2048
#define MROWS (BB*NN)
#define NEGINF (-1000000000.0f)
#define CAP  512

// ---------------- scratch (static device memory; no allocs) ----------------
__device__ float buf_h [MROWS*DDIM];
__device__ float buf_q [MROWS*DDIM];
__device__ float buf_k [MROWS*DDIM];
__device__ float buf_v [MROWS*DDIM];
__device__ float buf_o [MROWS*DDIM];
__device__ float buf_x [MROWS*DDIM];
__device__ float buf_ff[MROWS*DFFN];
__device__ int   buf_nbr[(size_t)MROWS*CAP];
__device__ int   buf_cnt[MROWS];
__device__ int   buf_bad[MROWS];
__device__ int   buf_nbad[BB];

// ---------------- cp.async helpers ----------------
__device__ __forceinline__ void cpa16(void* s, const void* g) {
    unsigned sa = (unsigned)__cvta_generic_to_shared(s);
    asm volatile("cp.async.cg.shared.global [%0], [%1], 16;\n" :: "r"(sa), "l"(g));
}
__device__ __forceinline__ void cpa_commit() {
    asm volatile("cp.async.commit_group;\n");
}
template<int N>
__device__ __forceinline__ void cpa_wait() {
    asm volatile("cp.async.wait_group %0;\n" :: "n"(N));
}

// ---------------- LayerNorm ----------------
__global__ __launch_bounds__(256) void ln_kernel(const float* __restrict__ X,
                                                 const float* __restrict__ gam,
                                                 const float* __restrict__ bet,
                                                 float* __restrict__ Y)
{
    int row = blockIdx.x;
    const float* x = X + (size_t)row * DDIM;
    int tid = threadIdx.x;
    float v0 = x[tid], v1 = x[tid + 256];

    __shared__ float red[8];
    __shared__ float stat[2];

    float s = v0 + v1;
    #pragma unroll
    for (int off = 16; off; off >>= 1) s += __shfl_xor_sync(0xffffffffu, s, off);
    if ((tid & 31) == 0) red[tid >> 5] = s;
    __syncthreads();
    if (tid < 8) {
        float t = red[tid];
        #pragma unroll
        for (int off = 4; off; off >>= 1) t += __shfl_xor_sync(0xffu, t, off);
        if (tid == 0) stat[0] = t * (1.0f / DDIM);
    }
    __syncthreads();
    float mean = stat[0];
    float d0 = v0 - mean, d1 = v1 - mean;
    float q = d0*d0 + d1*d1;
    #pragma unroll
    for (int off = 16; off; off >>= 1) q += __shfl_xor_sync(0xffffffffu, q, off);
    if ((tid & 31) == 0) red[tid >> 5] = q;
    __syncthreads();
    if (tid < 8) {
        float t = red[tid];
        #pragma unroll
        for (int off = 4; off; off >>= 1) t += __shfl_xor_sync(0xffu, t, off);
        if (tid == 0) stat[1] = rsqrtf(t * (1.0f / DDIM) + 1e-5f);
    }
    __syncthreads();
    float rs = stat[1];
    Y[(size_t)row*DDIM + tid]       = d0 * rs * gam[tid]       + bet[tid];
    Y[(size_t)row*DDIM + tid + 256] = d1 * rs * gam[tid + 256] + bet[tid + 256];
}

// ---------------- neighbor-list builder (one warp per query) + bad-list compaction ----------------
__global__ __launch_bounds__(256) void nbr_build_kernel(const float* __restrict__ xy,
                                                        const int* __restrict__ alive,
                                                        const int* __restrict__ species,
                                                        int* __restrict__ nbr,
                                                        int* __restrict__ cnt,
                                                        int* __restrict__ bad,
                                                        int* __restrict__ nbad)
{
    int b = blockIdx.y;
    int q = blockIdx.x * 8 + (threadIdx.x >> 5);
    int lane = threadIdx.x & 31;
    float xq = xy[(b*NN+q)*2], yq = xy[(b*NN+q)*2+1];
    int sq = species[b*NN+q];
    bool qa = sq < 2, qp = sq == 2;
    size_t base = (size_t)(b*NN + q) * CAP;
    int c = 0;
    for (int k0 = 0; k0 < NN; k0 += 32) {
        int k = k0 + lane;
        float xk = xy[(b*NN+k)*2], yk = xy[(b*NN+k)*2+1];
        bool un = alive[b*NN+k] != 0;
        float dx = __fadd_rn(xq, -xk), dy = __fadd_rn(yq, -yk);
        float d2 = __fadd_rn(__fmul_rn(dx,dx), __fmul_rn(dy,dy));
        if (d2 > 100.0f) un = false;
        int sk = species[b*NN+k];
        bool ka = sk < 2, kp = sk == 2;
        if ((qa && kp) || (qp && ka)) un = false;
        unsigned bal = __ballot_sync(0xffffffffu, un);
        int pos = c + __popc(bal & ((1u << lane) - 1u));
        if (un && pos < CAP) nbr[base + pos] = k;
        c += __popc(bal);
    }
    if (lane == 0) {
        cnt[b*NN + q] = (c > CAP) ? CAP : c;
        if (c == 0) {
            int p = atomicAdd(&nbad[b], 1);
            bad[b*NN + p] = q;
        }
    }
}

// ---------------- sparse gather attention: one warp per (b,h,query) ----------------
__global__ __launch_bounds__(256) void attn_sparse_kernel(const float* __restrict__ Q,
                                                          const float* __restrict__ Kg,
                                                          const float* __restrict__ Vg,
                                                          const int* __restrict__ nbr,
                                                          const int* __restrict__ cnt,
                                                          float* __restrict__ O)
{
    int b = blockIdx.z, h = blockIdx.y;
    int w = threadIdx.x >> 5, lane = threadIdx.x & 31;
    int q = blockIdx.x * 8 + w;

    __shared__ float Qs[8][DHH];
    __shared__ int   nbs[8][CAP];
    __shared__ float sc[8][CAP];

    size_t qrow = (size_t)(b*NN + q);
    int c = cnt[qrow];

    Qs[w][lane]      = Q[qrow*DDIM + h*DHH + lane];
    Qs[w][lane + 32] = Q[qrow*DDIM + h*DHH + lane + 32];
    for (int i = lane; i < c; i += 32) nbs[w][i] = nbr[qrow*CAP + i];
    __syncwarp();

    float mloc = -3.0e38f;
    for (int i = lane; i < c; i += 32) {
        int idx = nbs[w][i];
        const float4* kp = reinterpret_cast<const float4*>(&Kg[((size_t)(b*NN+idx))*DDIM + h*DHH]);
        float s = 0.f;
        #pragma unroll
        for (int d4 = 0; d4 < 16; d4++) {
            float4 kv = kp[d4];
            s += Qs[w][d4*4+0]*kv.x + Qs[w][d4*4+1]*kv.y
               + Qs[w][d4*4+2]*kv.z + Qs[w][d4*4+3]*kv.w;
        }
        s *= 0.125f;
        sc[w][i] = s;
        mloc = fmaxf(mloc, s);
    }
    #pragma unroll
    for (int off = 16; off; off >>= 1) mloc = fmaxf(mloc, __shfl_xor_sync(0xffffffffu, mloc, off));

    float lsum = 0.f;
    for (int i = lane; i < c; i += 32) {
        float p = expf(sc[w][i] - mloc);
        sc[w][i] = p;
        lsum += p;
    }
    #pragma unroll
    for (int off = 16; off; off >>= 1) lsum += __shfl_xor_sync(0xffffffffu, lsum, off);
    __syncwarp();

    float o0 = 0.f, o1 = 0.f;
    int j = 0;
    for (; j + 2 <= c; j += 2) {
        float w0 = sc[w][j], w1 = sc[w][j+1];
        int i0 = nbs[w][j], i1 = nbs[w][j+1];
        const float* v0p = &Vg[((size_t)(b*NN+i0))*DDIM + h*DHH];
        const float* v1p = &Vg[((size_t)(b*NN+i1))*DDIM + h*DHH];
        float a0 = v0p[lane], a1 = v0p[lane+32];
        float b0 = v1p[lane], b1 = v1p[lane+32];
        o0 += w0*a0 + w1*b0;
        o1 += w0*a1 + w1*b1;
    }
    for (; j < c; j++) {
        float wj = sc[w][j];
        const float* vp = &Vg[((size_t)(b*NN+nbs[w][j]))*DDIM + h*DHH];
        o0 += wj*vp[lane];
        o1 += wj*vp[lane+32];
    }

    float inv = (c > 0) ? 1.0f / lsum : 0.f;
    O[qrow*DDIM + h*DHH + lane]      = o0 * inv;
    O[qrow*DDIM + h*DHH + lane + 32] = o1 * inv;
}

// ---------------- fallback for zero-neighbor rows: compacted list, coalesced ----------------
__global__ __launch_bounds__(256) void attn_fallback(const float* __restrict__ Q,
                                                     const float* __restrict__ Kg,
                                                     const float* __restrict__ Vg,
                                                     const float* __restrict__ xy,
                                                     const int* __restrict__ alive,
                                                     const int* __restrict__ species,
                                                     const int* __restrict__ bad,
                                                     const int* __restrict__ nbad,
                                                     float* __restrict__ O)
{
    int b = blockIdx.y;
    int nb = nbad[b];
    int tid = threadIdx.x;
    int w = tid >> 5, lane = tid & 31;

    __shared__ float sc[NN];
    __shared__ float bs[NN];
    __shared__ float qs[DHH];
    __shared__ float vacc[4][DHH];
    __shared__ float red[8];
    __shared__ float stat[2];

    for (int it = blockIdx.x; it < nb; it += gridDim.x) {
        int q = bad[b*NN + it];
        float xq = xy[(b*NN+q)*2], yq = xy[(b*NN+q)*2+1];
        int sq = species[b*NN+q];
        bool qa = sq < 2, qp = sq == 2;

        // per-key bias (once per query, reused across heads)
        for (int k = tid; k < NN; k += 256) {
            float xk = xy[(b*NN+k)*2], yk = xy[(b*NN+k)*2+1];
            float bias = (alive[b*NN+k] == 0) ? NEGINF : 0.f;
            float dx = __fadd_rn(xq, -xk), dy = __fadd_rn(yq, -yk);
            float d2 = __fadd_rn(__fmul_rn(dx,dx), __fmul_rn(dy,dy));
            if (d2 > 100.0f) bias += NEGINF;
            int sk = species[b*NN+k];
            bool ka = sk < 2, kp = sk == 2;
            if ((qa && kp) || (qp && ka)) bias += NEGINF;
            bs[k] = bias;
        }
        __syncthreads();

        for (int h = 0; h < HH; h++) {
            if (tid < DHH) qs[tid] = Q[((size_t)(b*NN+q))*DDIM + h*DHH + tid];
            __syncthreads();

            // warp-per-key coalesced scores
            for (int k = w; k < NN; k += 8) {
                const float* kp = &Kg[((size_t)(b*NN+k))*DDIM + h*DHH];
                float p = qs[lane]*kp[lane] + qs[lane+32]*kp[lane+32];
                #pragma unroll
                for (int off = 16; off; off >>= 1) p += __shfl_xor_sync(0xffffffffu, p, off);
                if (lane == 0) sc[k] = p * 0.125f + bs[k];
            }
            __syncthreads();

            float mloc = -3.0e38f;
            for (int k = tid; k < NN; k += 256) mloc = fmaxf(mloc, sc[k]);
            #pragma unroll
            for (int off = 16; off; off >>= 1) mloc = fmaxf(mloc, __shfl_xor_sync(0xffffffffu, mloc, off));
            if ((tid & 31) == 0) red[tid >> 5] = mloc;
            __syncthreads();
            if (tid < 8) {
                float t = red[tid];
                #pragma unroll
                for (int off = 4; off; off >>= 1) t = fmaxf(t, __shfl_xor_sync(0xffu, t, off));
                if (tid == 0) stat[0] = t;
            }
            __syncthreads();
            float m = stat[0];
            float ls = 0.f;
            for (int k = tid; k < NN; k += 256) {
                float p = expf(sc[k] - m);
                sc[k] = p;
                ls += p;
            }
            #pragma unroll
            for (int off = 16; off; off >>= 1) ls += __shfl_xor_sync(0xffffffffu, ls, off);
            if ((tid & 31) == 0) red[tid >> 5] = ls;
            __syncthreads();
            if (tid < 8) {
                float t = red[tid];
                #pragma unroll
                for (int off = 4; off; off >>= 1) t += __shfl_xor_sync(0xffu, t, off);
                if (tid == 0) stat[1] = t;
            }
            __syncthreads();
            float inv = 1.0f / stat[1];

            // chunked coalesced V accumulation
            int cch = tid >> 6, d = tid & 63;
            float a = 0.f;
            int k0 = cch * 256;
            for (int k = k0; k < k0 + 256; k++)
                a += sc[k] * Vg[((size_t)(b*NN+k))*DDIM + h*DHH + d];
            vacc[cch][d] = a;
            __syncthreads();
            if (tid < DHH) {
                float o = vacc[0][tid] + vacc[1][tid] + vacc[2][tid] + vacc[3][tid];
                O[((size_t)(b*NN+q))*DDIM + h*DHH + tid] = o * inv;
            }
            __syncthreads();
        }
    }
}

// ---------------- tf32 GEMM: BM=128 BN=64 BK=16, cp.async 3-stage ----------------
#define GBM 128
#define GBN 64
#define GBK 16
#define ALD 20                      // 16 + 4 pad (80B rows, 16B-aligned)
#define BLD 72                      // 64 + 8 pad
#define STGF (GBM*ALD + GBK*BLD)    // 3712 floats per stage
#define GEMM_SMEM_BYTES (3 * STGF * 4)   // 44544 B

__device__ __forceinline__ float gelu_exact(float x) {
    return 0.5f * x * (1.0f + erff(x * 0.70710678118654752440f));
}

__device__ __forceinline__ void gemm_issue(const float* __restrict__ A,
                                           const float* __restrict__ W,
                                           int K, int Nc, int row0, int col0,
                                           int kt, float* stg, int tid)
{
    int k0 = kt * GBK;
    // A tile 128x16: 512 x 16B, 2 per thread
    #pragma unroll
    for (int i = 0; i < 2; i++) {
        int f = i * 256 + tid;
        int r = f >> 2, seg = (f & 3) * 4;
        cpa16(&stg[r * ALD + seg], &A[(size_t)(row0 + r) * K + k0 + seg]);
    }
    // B tile 16x64: 256 x 16B, 1 per thread
    {
        int r = tid >> 4, seg = (tid & 15) * 4;
        cpa16(&stg[GBM*ALD + r * BLD + seg], &W[(size_t)(k0 + r) * Nc + col0 + seg]);
    }
    cpa_commit();
}

__device__ __forceinline__ void gemm_core(const float* __restrict__ A,
                                          const float* __restrict__ W,
                                          const float* __restrict__ bias,
                                          const float* __restrict__ resid,
                                          float* __restrict__ C,
                                          int K, int Nc, int act,
                                          int row0, int col0, float* smem)
{
    int tid  = threadIdx.x;
    int warp = tid >> 5;
    int lane = tid & 31;
    int wm = warp >> 1;     // 0..3 -> 32-row slice
    int wn = warp & 1;      // 0..1 -> 32-col slice

    wmma::fragment<wmma::accumulator, 16,16,8, float> acc[2][2];
    #pragma unroll
    for (int mi = 0; mi < 2; mi++)
        #pragma unroll
        for (int ni = 0; ni < 2; ni++) wmma::fill_fragment(acc[mi][ni], 0.f);

    int niter = K / GBK;
    gemm_issue(A, W, K, Nc, row0, col0, 0, smem, tid);
    gemm_issue(A, W, K, Nc, row0, col0, 1, smem + STGF, tid);

    for (int kt = 0; kt < niter; kt++) {
        if (kt < niter - 1) cpa_wait<1>(); else cpa_wait<0>();
        __syncthreads();

        const float* st = smem + (kt % 3) * STGF;
        const float* Ac = st;
        const float* Bc = st + GBM*ALD;
        #pragma unroll
        for (int kk = 0; kk < GBK; kk += 8) {
            wmma::fragment<wmma::matrix_a, 16,16,8, wmma::precision::tf32, wmma::row_major> af[2];
            wmma::fragment<wmma::matrix_b, 16,16,8, wmma::precision::tf32, wmma::row_major> bf[2];
            #pragma unroll
            for (int mi = 0; mi < 2; mi++)
                wmma::load_matrix_sync(af[mi], &Ac[(wm*32 + mi*16) * ALD + kk], ALD);
            #pragma unroll
            for (int ni = 0; ni < 2; ni++)
                wmma::load_matrix_sync(bf[ni], &Bc[kk * BLD + wn*32 + ni*16], BLD);
            #pragma unroll
            for (int mi = 0; mi < 2; mi++)
                #pragma unroll
                for (int ni = 0; ni < 2; ni++)
                    wmma::mma_sync(acc[mi][ni], af[mi], bf[ni], acc[mi][ni]);
        }

        if (kt + 2 < niter) {
            // stage being written was last consumed at kt-1; all reads done at this kt's sync
            gemm_issue(A, W, K, Nc, row0, col0, kt + 2, smem + ((kt + 2) % 3) * STGF, tid);
        }
    }
    __syncthreads();

    // epilogue via per-warp staging (reuses stage memory)
    float* st = smem + warp * 256;
    #pragma unroll
    for (int mi = 0; mi < 2; mi++) {
        #pragma unroll
        for (int ni = 0; ni < 2; ni++) {
            wmma::store_matrix_sync(st, acc[mi][ni], 16, wmma::mem_row_major);
            __syncwarp();
            int gr0 = row0 + wm*32 + mi*16;
            int gc0 = col0 + wn*32 + ni*16;
            #pragma unroll
            for (int i = 0; i < 8; i++) {
                int idx = i*32 + lane;
                int r = idx >> 4, cc = idx & 15;
                float v = st[idx];
                if (bias)  v += bias[gc0 + cc];
                if (act)   v  = gelu_exact(v);
                if (resid) v += resid[(size_t)(gr0 + r) * Nc + gc0 + cc];
                C[(size_t)(gr0 + r) * Nc + gc0 + cc] = v;
            }
            __syncwarp();
        }
    }
}

__global__ __launch_bounds__(256, 2) void gemm_tc(const float* __restrict__ A,
                                                  const float* __restrict__ W,
                                                  const float* __restrict__ bias,
                                                  const float* __restrict__ resid,
                                                  float* __restrict__ C,
                                                  int K, int Nc, int act)
{
    extern __shared__ float smem[];
    gemm_core(A, W, bias, resid, C, K, Nc, act,
              blockIdx.y * GBM, blockIdx.x * GBN, smem);
}

__global__ __launch_bounds__(256, 2) void gemm_qkv(const float* __restrict__ A,
                                                   const float* __restrict__ Wq,
                                                   const float* __restrict__ Wk,
                                                   const float* __restrict__ Wv,
                                                   float* __restrict__ Cq,
                                                   float* __restrict__ Ck,
                                                   float* __restrict__ Cv)
{
    extern __shared__ float smem[];
    int z = blockIdx.z;
    const float* W = (z == 0) ? Wq : (z == 1) ? Wk : Wv;
    float*       C = (z == 0) ? Cq : (z == 1) ? Ck : Cv;
    gemm_core(A, W, nullptr, nullptr, C, DDIM, DDIM, 0,
              blockIdx.y * GBM, blockIdx.x * GBN, smem);
}

// ---------------- host orchestration ----------------
extern "C" void kernel_launch(void* const* d_in, const int* in_sizes, int n_in,
                              void* d_out, int out_size)
{
    (void)in_sizes; (void)n_in; (void)out_size;
    const float* tokens  = (const float*)d_in[0];
    const float* xy      = (const float*)d_in[1];
    const float* Wq      = (const float*)d_in[2];
    const float* Wk      = (const float*)d_in[3];
    const float* Wv      = (const float*)d_in[4];
    const float* Wo      = (const float*)d_in[5];
    const float* bo      = (const float*)d_in[6];
    const float* W1      = (const float*)d_in[7];
    const float* b1      = (const float*)d_in[8];
    const float* W2      = (const float*)d_in[9];
    const float* b2      = (const float*)d_in[10];
    const float* g1      = (const float*)d_in[11];
    const float* be1     = (const float*)d_in[12];
    const float* g2      = (const float*)d_in[13];
    const float* be2     = (const float*)d_in[14];
    const float* gf      = (const float*)d_in[15];
    const float* bf      = (const float*)d_in[16];
    const int*   alive   = (const int*)d_in[17];
    const int*   species = (const int*)d_in[18];

    float *p_h, *p_q, *p_k, *p_v, *p_o, *p_x, *p_ff;
    int *p_nbr, *p_cnt, *p_bad, *p_nbad;
    cudaGetSymbolAddress((void**)&p_h,  buf_h);
    cudaGetSymbolAddress((void**)&p_q,  buf_q);
    cudaGetSymbolAddress((void**)&p_k,  buf_k);
    cudaGetSymbolAddress((void**)&p_v,  buf_v);
    cudaGetSymbolAddress((void**)&p_o,  buf_o);
    cudaGetSymbolAddress((void**)&p_x,  buf_x);
    cudaGetSymbolAddress((void**)&p_ff, buf_ff);
    cudaGetSymbolAddress((void**)&p_nbr, buf_nbr);
    cudaGetSymbolAddress((void**)&p_cnt, buf_cnt);
    cudaGetSymbolAddress((void**)&p_bad, buf_bad);
    cudaGetSymbolAddress((void**)&p_nbad, buf_nbad);

    static int smem_set = 0;
    if (!smem_set) {
        cudaFuncSetAttribute(gemm_tc,  cudaFuncAttributeMaxDynamicSharedMemorySize, GEMM_SMEM_BYTES);
        cudaFuncSetAttribute(gemm_qkv, cudaFuncAttributeMaxDynamicSharedMemorySize, GEMM_SMEM_BYTES);
        smem_set = 1;
    }

    const int M = MROWS;
    dim3 gD(DDIM / GBN, M / GBM);        // (8, 32) = 256
    dim3 gQKV(DDIM / GBN, M / GBM, 3);   // 768
    dim3 gF(DFFN / GBN, M / GBM);        // (32, 32) = 1024
    dim3 attnG(NN / 8, HH, BB);
    dim3 fbG(32, BB);

    cudaMemsetAsync(p_nbad, 0, BB * sizeof(int));
    nbr_build_kernel<<<dim3(NN/8, BB), 256>>>(xy, alive, species, p_nbr, p_cnt, p_bad, p_nbad);

    for (int l = 0; l < LLAY; l++) {
        const float* xsrc = (l == 0) ? tokens : p_x;
        const float* Wq_l = Wq + (size_t)l * DDIM * DDIM;
        const float* Wk_l = Wk + (size_t)l * DDIM * DDIM;
        const float* Wv_l = Wv + (size_t)l * DDIM * DDIM;
        const float* Wo_l = Wo + (size_t)l * DDIM * DDIM;
        const float* W1_l = W1 + (size_t)l * DDIM * DFFN;
        const float* W2_l = W2 + (size_t)l * DFFN * DDIM;

        ln_kernel<<<M, 256>>>(xsrc, g1 + l * DDIM, be1 + l * DDIM, p_h);

        gemm_qkv<<<gQKV, 256, GEMM_SMEM_BYTES>>>(p_h, Wq_l, Wk_l, Wv_l, p_q, p_k, p_v);

        attn_sparse_kernel<<<attnG, 256>>>(p_q, p_k, p_v, p_nbr, p_cnt, p_o);
        attn_fallback<<<fbG, 256>>>(p_q, p_k, p_v, xy, alive, species, p_bad, p_nbad, p_o);

        gemm_tc<<<gD, 256, GEMM_SMEM_BYTES>>>(p_o, Wo_l, bo + l * DDIM, xsrc, p_x, DDIM, DDIM, 0);

        ln_kernel<<<M, 256>>>(p_x, g2 + l * DDIM, be2 + l * DDIM, p_h);

        gemm_tc<<<gF, 256, GEMM_SMEM_BYTES>>>(p_h, W1_l, b1 + l * DFFN, nullptr, p_ff, DDIM, DFFN, 1);
        gemm_tc<<<gD, 256, GEMM_SMEM_BYTES>>>(p_ff, W2_l, b2 + l * DDIM, p_x, p_x, DFFN, DDIM, 0);
    }

    ln_kernel<<<M, 256>>>(p_x, gf, bf, (float*)d_out);
}

// round 11
// speedup vs baseline: 1.7524x; 1.4487x over previous
#include <cuda_runtime.h>
#include <cuda_fp16.h>
#include <mma.h>
using namespace nvcuda;

#define BB   4
#define NN   1024
#define DDIM 512
#define HH   8
#define DHH  64
#define LLAY 6
#define DFFN 2048
#define MROWS (BB*NN)
#define NEGINF (-1000000000.0f)
#define CAP  512

// ---------------- scratch (static device memory; no allocs) ----------------
__device__ __half buf_h [MROWS*DDIM];     // LN output (GEMM A)
__device__ float  buf_q [MROWS*DDIM];
__device__ float  buf_k [MROWS*DDIM];
__device__ float  buf_v [MROWS*DDIM];
__device__ __half buf_o [MROWS*DDIM];     // attention output (GEMM A)
__device__ float  buf_x [MROWS*DDIM];
__device__ __half buf_ff[MROWS*DFFN];     // gelu output (GEMM A)
__device__ int    buf_nbr[(size_t)MROWS*CAP];
__device__ int    buf_cnt[MROWS];
__device__ int    buf_bad[MROWS];
__device__ int    buf_nbad[BB];
// half weights (converted once per launch)
__device__ __half buf_wq[(size_t)LLAY*DDIM*DDIM];
__device__ __half buf_wk[(size_t)LLAY*DDIM*DDIM];
__device__ __half buf_wv[(size_t)LLAY*DDIM*DDIM];
__device__ __half buf_wo[(size_t)LLAY*DDIM*DDIM];
__device__ __half buf_w1[(size_t)LLAY*DDIM*DFFN];
__device__ __half buf_w2[(size_t)LLAY*DFFN*DDIM];

// ---------------- cp.async helpers ----------------
__device__ __forceinline__ void cpa16(void* s, const void* g) {
    unsigned sa = (unsigned)__cvta_generic_to_shared(s);
    asm volatile("cp.async.cg.shared.global [%0], [%1], 16;\n" :: "r"(sa), "l"(g));
}
__device__ __forceinline__ void cpa_commit() {
    asm volatile("cp.async.commit_group;\n");
}
template<int N>
__device__ __forceinline__ void cpa_wait() {
    asm volatile("cp.async.wait_group %0;\n" :: "n"(N));
}

// ---------------- fp32 -> fp16 conversion ----------------
__global__ __launch_bounds__(256) void f2h_kernel(const float* __restrict__ src,
                                                  __half* __restrict__ dst, int n)
{
    int stride = gridDim.x * blockDim.x * 4;
    for (int i = (blockIdx.x * blockDim.x + threadIdx.x) * 4; i < n; i += stride) {
        float4 v = *reinterpret_cast<const float4*>(src + i);
        __half2* d = reinterpret_cast<__half2*>(dst + i);
        d[0] = __floats2half2_rn(v.x, v.y);
        d[1] = __floats2half2_rn(v.z, v.w);
    }
}

// ---------------- LayerNorm (templated output type) ----------------
template<typename OutT>
__global__ __launch_bounds__(256) void ln_kernel(const float* __restrict__ X,
                                                 const float* __restrict__ gam,
                                                 const float* __restrict__ bet,
                                                 OutT* __restrict__ Y)
{
    int row = blockIdx.x;
    const float* x = X + (size_t)row * DDIM;
    int tid = threadIdx.x;
    float v0 = x[tid], v1 = x[tid + 256];

    __shared__ float red[8];
    __shared__ float stat[2];

    float s = v0 + v1;
    #pragma unroll
    for (int off = 16; off; off >>= 1) s += __shfl_xor_sync(0xffffffffu, s, off);
    if ((tid & 31) == 0) red[tid >> 5] = s;
    __syncthreads();
    if (tid < 8) {
        float t = red[tid];
        #pragma unroll
        for (int off = 4; off; off >>= 1) t += __shfl_xor_sync(0xffu, t, off);
        if (tid == 0) stat[0] = t * (1.0f / DDIM);
    }
    __syncthreads();
    float mean = stat[0];
    float d0 = v0 - mean, d1 = v1 - mean;
    float q = d0*d0 + d1*d1;
    #pragma unroll
    for (int off = 16; off; off >>= 1) q += __shfl_xor_sync(0xffffffffu, q, off);
    if ((tid & 31) == 0) red[tid >> 5] = q;
    __syncthreads();
    if (tid < 8) {
        float t = red[tid];
        #pragma unroll
        for (int off = 4; off; off >>= 1) t += __shfl_xor_sync(0xffu, t, off);
        if (tid == 0) stat[1] = rsqrtf(t * (1.0f / DDIM) + 1e-5f);
    }
    __syncthreads();
    float rs = stat[1];
    float y0 = d0 * rs * gam[tid]       + bet[tid];
    float y1 = d1 * rs * gam[tid + 256] + bet[tid + 256];
    if constexpr (sizeof(OutT) == 2) {
        Y[(size_t)row*DDIM + tid]       = __float2half_rn(y0);
        Y[(size_t)row*DDIM + tid + 256] = __float2half_rn(y1);
    } else {
        Y[(size_t)row*DDIM + tid]       = y0;
        Y[(size_t)row*DDIM + tid + 256] = y1;
    }
}

// ---------------- neighbor-list builder + bad-list compaction ----------------
__global__ __launch_bounds__(256) void nbr_build_kernel(const float* __restrict__ xy,
                                                        const int* __restrict__ alive,
                                                        const int* __restrict__ species,
                                                        int* __restrict__ nbr,
                                                        int* __restrict__ cnt,
                                                        int* __restrict__ bad,
                                                        int* __restrict__ nbad)
{
    int b = blockIdx.y;
    int q = blockIdx.x * 8 + (threadIdx.x >> 5);
    int lane = threadIdx.x & 31;
    float xq = xy[(b*NN+q)*2], yq = xy[(b*NN+q)*2+1];
    int sq = species[b*NN+q];
    bool qa = sq < 2, qp = sq == 2;
    size_t base = (size_t)(b*NN + q) * CAP;
    int c = 0;
    for (int k0 = 0; k0 < NN; k0 += 32) {
        int k = k0 + lane;
        float xk = xy[(b*NN+k)*2], yk = xy[(b*NN+k)*2+1];
        bool un = alive[b*NN+k] != 0;
        float dx = __fadd_rn(xq, -xk), dy = __fadd_rn(yq, -yk);
        float d2 = __fadd_rn(__fmul_rn(dx,dx), __fmul_rn(dy,dy));
        if (d2 > 100.0f) un = false;
        int sk = species[b*NN+k];
        bool ka = sk < 2, kp = sk == 2;
        if ((qa && kp) || (qp && ka)) un = false;
        unsigned bal = __ballot_sync(0xffffffffu, un);
        int pos = c + __popc(bal & ((1u << lane) - 1u));
        if (un && pos < CAP) nbr[base + pos] = k;
        c += __popc(bal);
    }
    if (lane == 0) {
        cnt[b*NN + q] = (c > CAP) ? CAP : c;
        if (c == 0) {
            int p = atomicAdd(&nbad[b], 1);
            bad[b*NN + p] = q;
        }
    }
}

// ---------------- sparse gather attention: one warp per (b,h,query) ----------------
__global__ __launch_bounds__(256) void attn_sparse_kernel(const float* __restrict__ Q,
                                                          const float* __restrict__ Kg,
                                                          const float* __restrict__ Vg,
                                                          const int* __restrict__ nbr,
                                                          const int* __restrict__ cnt,
                                                          __half* __restrict__ O)
{
    int b = blockIdx.z, h = blockIdx.y;
    int w = threadIdx.x >> 5, lane = threadIdx.x & 31;
    int q = blockIdx.x * 8 + w;

    __shared__ float Qs[8][DHH];
    __shared__ int   nbs[8][CAP];
    __shared__ float sc[8][CAP];

    size_t qrow = (size_t)(b*NN + q);
    int c = cnt[qrow];

    Qs[w][lane]      = Q[qrow*DDIM + h*DHH + lane];
    Qs[w][lane + 32] = Q[qrow*DDIM + h*DHH + lane + 32];
    for (int i = lane; i < c; i += 32) nbs[w][i] = nbr[qrow*CAP + i];
    __syncwarp();

    float mloc = -3.0e38f;
    for (int i = lane; i < c; i += 32) {
        int idx = nbs[w][i];
        const float4* kp = reinterpret_cast<const float4*>(&Kg[((size_t)(b*NN+idx))*DDIM + h*DHH]);
        float s = 0.f;
        #pragma unroll
        for (int d4 = 0; d4 < 16; d4++) {
            float4 kv = kp[d4];
            s += Qs[w][d4*4+0]*kv.x + Qs[w][d4*4+1]*kv.y
               + Qs[w][d4*4+2]*kv.z + Qs[w][d4*4+3]*kv.w;
        }
        s *= 0.125f;
        sc[w][i] = s;
        mloc = fmaxf(mloc, s);
    }
    #pragma unroll
    for (int off = 16; off; off >>= 1) mloc = fmaxf(mloc, __shfl_xor_sync(0xffffffffu, mloc, off));

    float lsum = 0.f;
    for (int i = lane; i < c; i += 32) {
        float p = expf(sc[w][i] - mloc);
        sc[w][i] = p;
        lsum += p;
    }
    #pragma unroll
    for (int off = 16; off; off >>= 1) lsum += __shfl_xor_sync(0xffffffffu, lsum, off);
    __syncwarp();

    float o0 = 0.f, o1 = 0.f;
    int j = 0;
    for (; j + 2 <= c; j += 2) {
        float w0 = sc[w][j], w1 = sc[w][j+1];
        int i0 = nbs[w][j], i1 = nbs[w][j+1];
        const float* v0p = &Vg[((size_t)(b*NN+i0))*DDIM + h*DHH];
        const float* v1p = &Vg[((size_t)(b*NN+i1))*DDIM + h*DHH];
        float a0 = v0p[lane], a1 = v0p[lane+32];
        float b0 = v1p[lane], b1 = v1p[lane+32];
        o0 += w0*a0 + w1*b0;
        o1 += w0*a1 + w1*b1;
    }
    for (; j < c; j++) {
        float wj = sc[w][j];
        const float* vp = &Vg[((size_t)(b*NN+nbs[w][j]))*DDIM + h*DHH];
        o0 += wj*vp[lane];
        o1 += wj*vp[lane+32];
    }

    float inv = (c > 0) ? 1.0f / lsum : 0.f;
    O[qrow*DDIM + h*DHH + lane]      = __float2half_rn(o0 * inv);
    O[qrow*DDIM + h*DHH + lane + 32] = __float2half_rn(o1 * inv);
}

// ---------------- fallback for zero-neighbor rows: compacted list, coalesced ----------------
__global__ __launch_bounds__(256) void attn_fallback(const float* __restrict__ Q,
                                                     const float* __restrict__ Kg,
                                                     const float* __restrict__ Vg,
                                                     const float* __restrict__ xy,
                                                     const int* __restrict__ alive,
                                                     const int* __restrict__ species,
                                                     const int* __restrict__ bad,
                                                     const int* __restrict__ nbad,
                                                     __half* __restrict__ O)
{
    int b = blockIdx.y;
    int nb = nbad[b];
    int tid = threadIdx.x;
    int w = tid >> 5, lane = tid & 31;

    __shared__ float sc[NN];
    __shared__ float bs[NN];
    __shared__ float qs[DHH];
    __shared__ float vacc[4][DHH];
    __shared__ float red[8];
    __shared__ float stat[2];

    for (int it = blockIdx.x; it < nb; it += gridDim.x) {
        int q = bad[b*NN + it];
        float xq = xy[(b*NN+q)*2], yq = xy[(b*NN+q)*2+1];
        int sq = species[b*NN+q];
        bool qa = sq < 2, qp = sq == 2;

        for (int k = tid; k < NN; k += 256) {
            float xk = xy[(b*NN+k)*2], yk = xy[(b*NN+k)*2+1];
            float bias = (alive[b*NN+k] == 0) ? NEGINF : 0.f;
            float dx = __fadd_rn(xq, -xk), dy = __fadd_rn(yq, -yk);
            float d2 = __fadd_rn(__fmul_rn(dx,dx), __fmul_rn(dy,dy));
            if (d2 > 100.0f) bias += NEGINF;
            int sk = species[b*NN+k];
            bool ka = sk < 2, kp = sk == 2;
            if ((qa && kp) || (qp && ka)) bias += NEGINF;
            bs[k] = bias;
        }
        __syncthreads();

        for (int h = 0; h < HH; h++) {
            if (tid < DHH) qs[tid] = Q[((size_t)(b*NN+q))*DDIM + h*DHH + tid];
            __syncthreads();

            for (int k = w; k < NN; k += 8) {
                const float* kp = &Kg[((size_t)(b*NN+k))*DDIM + h*DHH];
                float p = qs[lane]*kp[lane] + qs[lane+32]*kp[lane+32];
                #pragma unroll
                for (int off = 16; off; off >>= 1) p += __shfl_xor_sync(0xffffffffu, p, off);
                if (lane == 0) sc[k] = p * 0.125f + bs[k];
            }
            __syncthreads();

            float mloc = -3.0e38f;
            for (int k = tid; k < NN; k += 256) mloc = fmaxf(mloc, sc[k]);
            #pragma unroll
            for (int off = 16; off; off >>= 1) mloc = fmaxf(mloc, __shfl_xor_sync(0xffffffffu, mloc, off));
            if ((tid & 31) == 0) red[tid >> 5] = mloc;
            __syncthreads();
            if (tid < 8) {
                float t = red[tid];
                #pragma unroll
                for (int off = 4; off; off >>= 1) t = fmaxf(t, __shfl_xor_sync(0xffu, t, off));
                if (tid == 0) stat[0] = t;
            }
            __syncthreads();
            float m = stat[0];
            float ls = 0.f;
            for (int k = tid; k < NN; k += 256) {
                float p = expf(sc[k] - m);
                sc[k] = p;
                ls += p;
            }
            #pragma unroll
            for (int off = 16; off; off >>= 1) ls += __shfl_xor_sync(0xffffffffu, ls, off);
            if ((tid & 31) == 0) red[tid >> 5] = ls;
            __syncthreads();
            if (tid < 8) {
                float t = red[tid];
                #pragma unroll
                for (int off = 4; off; off >>= 1) t += __shfl_xor_sync(0xffu, t, off);
                if (tid == 0) stat[1] = t;
            }
            __syncthreads();
            float inv = 1.0f / stat[1];

            int cch = tid >> 6, d = tid & 63;
            float a = 0.f;
            int k0 = cch * 256;
            for (int k = k0; k < k0 + 256; k++)
                a += sc[k] * Vg[((size_t)(b*NN+k))*DDIM + h*DHH + d];
            vacc[cch][d] = a;
            __syncthreads();
            if (tid < DHH) {
                float o = vacc[0][tid] + vacc[1][tid] + vacc[2][tid] + vacc[3][tid];
                O[((size_t)(b*NN+q))*DDIM + h*DHH + tid] = __float2half_rn(o * inv);
            }
            __syncthreads();
        }
    }
}

// ---------------- fp16 GEMM: BM=128 BN=64 BK=32, cp.async 3-stage ----------------
#define GBM 128
#define GBN 64
#define GBK 32
#define ALD 40                       // 32 + 8 pad halves (80 B rows)
#define BLD 72                       // 64 + 8 pad halves (144 B rows)
#define A_STG_BYTES (GBM*ALD*2)      // 10240
#define B_STG_BYTES (GBK*BLD*2)      // 4608
#define STG_BYTES (A_STG_BYTES + B_STG_BYTES)   // 14848
#define GEMM_SMEM_BYTES (3 * STG_BYTES)         // 44544

__device__ __forceinline__ float gelu_exact(float x) {
    return 0.5f * x * (1.0f + erff(x * 0.70710678118654752440f));
}

__device__ __forceinline__ void gemm_issue(const __half* __restrict__ A,
                                           const __half* __restrict__ W,
                                           int K, int Nc, int row0, int col0,
                                           int kt, char* stg, int tid)
{
    int k0 = kt * GBK;
    __half* As = reinterpret_cast<__half*>(stg);
    __half* Bs = reinterpret_cast<__half*>(stg + A_STG_BYTES);
    // A tile 128x32 halves: 512 x 16B chunks, 2 per thread
    #pragma unroll
    for (int i = 0; i < 2; i++) {
        int f = i * 256 + tid;
        int r = f >> 2, seg = (f & 3) * 8;
        cpa16(&As[r * ALD + seg], &A[(size_t)(row0 + r) * K + k0 + seg]);
    }
    // B tile 32x64 halves: 256 x 16B chunks, 1 per thread
    {
        int r = tid >> 3, seg = (tid & 7) * 8;
        cpa16(&Bs[r * BLD + seg], &W[(size_t)(k0 + r) * Nc + col0 + seg]);
    }
    cpa_commit();
}

template<typename OutT>
__device__ __forceinline__ void gemm_core(const __half* __restrict__ A,
                                          const __half* __restrict__ W,
                                          const float* __restrict__ bias,
                                          const float* __restrict__ resid,
                                          OutT* __restrict__ C,
                                          int K, int Nc, int act,
                                          int row0, int col0, char* smem)
{
    int tid  = threadIdx.x;
    int warp = tid >> 5;
    int lane = tid & 31;
    int wm = warp >> 1;     // 0..3 -> 32-row slice
    int wn = warp & 1;      // 0..1 -> 32-col slice

    wmma::fragment<wmma::accumulator, 16,16,16, float> acc[2][2];
    #pragma unroll
    for (int mi = 0; mi < 2; mi++)
        #pragma unroll
        for (int ni = 0; ni < 2; ni++) wmma::fill_fragment(acc[mi][ni], 0.f);

    int niter = K / GBK;
    gemm_issue(A, W, K, Nc, row0, col0, 0, smem, tid);
    gemm_issue(A, W, K, Nc, row0, col0, 1, smem + STG_BYTES, tid);

    for (int kt = 0; kt < niter; kt++) {
        if (kt < niter - 1) cpa_wait<1>(); else cpa_wait<0>();
        __syncthreads();

        char* st = smem + (kt % 3) * STG_BYTES;
        const __half* Ac = reinterpret_cast<const __half*>(st);
        const __half* Bc = reinterpret_cast<const __half*>(st + A_STG_BYTES);
        #pragma unroll
        for (int kk = 0; kk < GBK; kk += 16) {
            wmma::fragment<wmma::matrix_a, 16,16,16, __half, wmma::row_major> af[2];
            wmma::fragment<wmma::matrix_b, 16,16,16, __half, wmma::row_major> bf[2];
            #pragma unroll
            for (int mi = 0; mi < 2; mi++)
                wmma::load_matrix_sync(af[mi], &Ac[(wm*32 + mi*16) * ALD + kk], ALD);
            #pragma unroll
            for (int ni = 0; ni < 2; ni++)
                wmma::load_matrix_sync(bf[ni], &Bc[kk * BLD + wn*32 + ni*16], BLD);
            #pragma unroll
            for (int mi = 0; mi < 2; mi++)
                #pragma unroll
                for (int ni = 0; ni < 2; ni++)
                    wmma::mma_sync(acc[mi][ni], af[mi], bf[ni], acc[mi][ni]);
        }

        if (kt + 2 < niter)
            gemm_issue(A, W, K, Nc, row0, col0, kt + 2, smem + ((kt + 2) % 3) * STG_BYTES, tid);
    }
    __syncthreads();

    // epilogue via per-warp staging (reuses stage memory; 8 KB < stage bytes)
    float* st = reinterpret_cast<float*>(smem) + warp * 256;
    #pragma unroll
    for (int mi = 0; mi < 2; mi++) {
        #pragma unroll
        for (int ni = 0; ni < 2; ni++) {
            wmma::store_matrix_sync(st, acc[mi][ni], 16, wmma::mem_row_major);
            __syncwarp();
            int gr0 = row0 + wm*32 + mi*16;
            int gc0 = col0 + wn*32 + ni*16;
            #pragma unroll
            for (int i = 0; i < 8; i++) {
                int idx = i*32 + lane;
                int r = idx >> 4, cc = idx & 15;
                float v = st[idx];
                if (bias)  v += bias[gc0 + cc];
                if (act)   v  = gelu_exact(v);
                if (resid) v += resid[(size_t)(gr0 + r) * Nc + gc0 + cc];
                if constexpr (sizeof(OutT) == 2)
                    C[(size_t)(gr0 + r) * Nc + gc0 + cc] = __float2half_rn(v);
                else
                    C[(size_t)(gr0 + r) * Nc + gc0 + cc] = v;
            }
            __syncwarp();
        }
    }
}

__global__ __launch_bounds__(256, 2) void gemm_f32(const __half* __restrict__ A,
                                                   const __half* __restrict__ W,
                                                   const float* __restrict__ bias,
                                                   const float* __restrict__ resid,
                                                   float* __restrict__ C,
                                                   int K, int Nc, int act)
{
    extern __shared__ char smem[];
    gemm_core<float>(A, W, bias, resid, C, K, Nc, act,
                     blockIdx.y * GBM, blockIdx.x * GBN, smem);
}

__global__ __launch_bounds__(256, 2) void gemm_f16(const __half* __restrict__ A,
                                                   const __half* __restrict__ W,
                                                   const float* __restrict__ bias,
                                                   const float* __restrict__ resid,
                                                   __half* __restrict__ C,
                                                   int K, int Nc, int act)
{
    extern __shared__ char smem[];
    gemm_core<__half>(A, W, bias, resid, C, K, Nc, act,
                      blockIdx.y * GBM, blockIdx.x * GBN, smem);
}

__global__ __launch_bounds__(256, 2) void gemm_qkv(const __half* __restrict__ A,
                                                   const __half* __restrict__ Wq,
                                                   const __half* __restrict__ Wk,
                                                   const __half* __restrict__ Wv,
                                                   float* __restrict__ Cq,
                                                   float* __restrict__ Ck,
                                                   float* __restrict__ Cv)
{
    extern __shared__ char smem[];
    int z = blockIdx.z;
    const __half* W = (z == 0) ? Wq : (z == 1) ? Wk : Wv;
    float*        C = (z == 0) ? Cq : (z == 1) ? Ck : Cv;
    gemm_core<float>(A, W, nullptr, nullptr, C, DDIM, DDIM, 0,
                     blockIdx.y * GBM, blockIdx.x * GBN, smem);
}

// ---------------- host orchestration ----------------
extern "C" void kernel_launch(void* const* d_in, const int* in_sizes, int n_in,
                              void* d_out, int out_size)
{
    (void)in_sizes; (void)n_in; (void)out_size;
    const float* tokens  = (const float*)d_in[0];
    const float* xy      = (const float*)d_in[1];
    const float* Wq      = (const float*)d_in[2];
    const float* Wk      = (const float*)d_in[3];
    const float* Wv      = (const float*)d_in[4];
    const float* Wo      = (const float*)d_in[5];
    const float* bo      = (const float*)d_in[6];
    const float* W1      = (const float*)d_in[7];
    const float* b1      = (const float*)d_in[8];
    const float* W2      = (const float*)d_in[9];
    const float* b2      = (const float*)d_in[10];
    const float* g1      = (const float*)d_in[11];
    const float* be1     = (const float*)d_in[12];
    const float* g2      = (const float*)d_in[13];
    const float* be2     = (const float*)d_in[14];
    const float* gf      = (const float*)d_in[15];
    const float* bf      = (const float*)d_in[16];
    const int*   alive   = (const int*)d_in[17];
    const int*   species = (const int*)d_in[18];

    __half *p_h, *p_o, *p_ff, *p_wq, *p_wk, *p_wv, *p_wo, *p_w1, *p_w2;
    float *p_q, *p_k, *p_v, *p_x;
    int *p_nbr, *p_cnt, *p_bad, *p_nbad;
    cudaGetSymbolAddress((void**)&p_h,  buf_h);
    cudaGetSymbolAddress((void**)&p_q,  buf_q);
    cudaGetSymbolAddress((void**)&p_k,  buf_k);
    cudaGetSymbolAddress((void**)&p_v,  buf_v);
    cudaGetSymbolAddress((void**)&p_o,  buf_o);
    cudaGetSymbolAddress((void**)&p_x,  buf_x);
    cudaGetSymbolAddress((void**)&p_ff, buf_ff);
    cudaGetSymbolAddress((void**)&p_nbr, buf_nbr);
    cudaGetSymbolAddress((void**)&p_cnt, buf_cnt);
    cudaGetSymbolAddress((void**)&p_bad, buf_bad);
    cudaGetSymbolAddress((void**)&p_nbad, buf_nbad);
    cudaGetSymbolAddress((void**)&p_wq, buf_wq);
    cudaGetSymbolAddress((void**)&p_wk, buf_wk);
    cudaGetSymbolAddress((void**)&p_wv, buf_wv);
    cudaGetSymbolAddress((void**)&p_wo, buf_wo);
    cudaGetSymbolAddress((void**)&p_w1, buf_w1);
    cudaGetSymbolAddress((void**)&p_w2, buf_w2);

    static int smem_set = 0;
    if (!smem_set) {
        cudaFuncSetAttribute(gemm_f32, cudaFuncAttributeMaxDynamicSharedMemorySize, GEMM_SMEM_BYTES);
        cudaFuncSetAttribute(gemm_f16, cudaFuncAttributeMaxDynamicSharedMemorySize, GEMM_SMEM_BYTES);
        cudaFuncSetAttribute(gemm_qkv, cudaFuncAttributeMaxDynamicSharedMemorySize, GEMM_SMEM_BYTES);
        smem_set = 1;
    }

    const int M = MROWS;
    const int NDD = LLAY * DDIM * DDIM;       // 1,572,864
    const int NDF = LLAY * DDIM * DFFN;       // 6,291,456

    // weight conversion (RN) — once per launch
    f2h_kernel<<<512, 256>>>(Wq, p_wq, NDD);
    f2h_kernel<<<512, 256>>>(Wk, p_wk, NDD);
    f2h_kernel<<<512, 256>>>(Wv, p_wv, NDD);
    f2h_kernel<<<512, 256>>>(Wo, p_wo, NDD);
    f2h_kernel<<<1024, 256>>>(W1, p_w1, NDF);
    f2h_kernel<<<1024, 256>>>(W2, p_w2, NDF);

    dim3 gD(DDIM / GBN, M / GBM);        // (8, 32) = 256
    dim3 gQKV(DDIM / GBN, M / GBM, 3);   // 768
    dim3 gF(DFFN / GBN, M / GBM);        // (32, 32) = 1024
    dim3 attnG(NN / 8, HH, BB);
    dim3 fbG(32, BB);

    cudaMemsetAsync(p_nbad, 0, BB * sizeof(int));
    nbr_build_kernel<<<dim3(NN/8, BB), 256>>>(xy, alive, species, p_nbr, p_cnt, p_bad, p_nbad);

    for (int l = 0; l < LLAY; l++) {
        const float* xsrc = (l == 0) ? tokens : p_x;
        size_t offD = (size_t)l * DDIM * DDIM;
        size_t offF = (size_t)l * DDIM * DFFN;

        ln_kernel<__half><<<M, 256>>>(xsrc, g1 + l * DDIM, be1 + l * DDIM, p_h);

        gemm_qkv<<<gQKV, 256, GEMM_SMEM_BYTES>>>(p_h, p_wq + offD, p_wk + offD, p_wv + offD,
                                                 p_q, p_k, p_v);

        attn_sparse_kernel<<<attnG, 256>>>(p_q, p_k, p_v, p_nbr, p_cnt, p_o);
        attn_fallback<<<fbG, 256>>>(p_q, p_k, p_v, xy, alive, species, p_bad, p_nbad, p_o);

        gemm_f32<<<gD, 256, GEMM_SMEM_BYTES>>>(p_o, p_wo + offD, bo + l * DDIM, xsrc, p_x,
                                               DDIM, DDIM, 0);

        ln_kernel<__half><<<M, 256>>>(p_x, g2 + l * DDIM, be2 + l * DDIM, p_h);

        gemm_f16<<<gF, 256, GEMM_SMEM_BYTES>>>(p_h, p_w1 + offF, b1 + l * DFFN, nullptr, p_ff,
                                               DDIM, DFFN, 1);
        gemm_f32<<<gD, 256, GEMM_SMEM_BYTES>>>(p_ff, p_w2 + offF, b2 + l * DDIM, p_x, p_x,
                                               DFFN, DDIM, 0);
    }

    ln_kernel<float><<<M, 256>>>(p_x, gf, bf, (float*)d_out);
}

// round 12
// speedup vs baseline: 1.8356x; 1.0475x over previous
#include <cuda_runtime.h>
#include <cuda_fp16.h>
#include <mma.h>
using namespace nvcuda;

#define BB   4
#define NN   1024
#define DDIM 512
#define HH   8
#define DHH  64
#define LLAY 6
#define DFFN 2048
#define MROWS (BB*NN)
#define NEGINF (-1000000000.0f)
#define CAP  512
#define NSLOT 16   // CAP/32

// ---------------- scratch (static device memory; no allocs) ----------------
__device__ __half buf_h [MROWS*DDIM];
__device__ __half buf_q [MROWS*DDIM];
__device__ __half buf_k [MROWS*DDIM];
__device__ __half buf_v [MROWS*DDIM];
__device__ __half buf_o [MROWS*DDIM];
__device__ float  buf_x [MROWS*DDIM];
__device__ __half buf_ff[MROWS*DFFN];
__device__ int    buf_nbr[(size_t)MROWS*CAP];
__device__ int    buf_cnt[MROWS];
__device__ int    buf_bad[MROWS];
__device__ int    buf_nbad[BB];
__device__ __half buf_wq[(size_t)LLAY*DDIM*DDIM];
__device__ __half buf_wk[(size_t)LLAY*DDIM*DDIM];
__device__ __half buf_wv[(size_t)LLAY*DDIM*DDIM];
__device__ __half buf_wo[(size_t)LLAY*DDIM*DDIM];
__device__ __half buf_w1[(size_t)LLAY*DDIM*DFFN];
__device__ __half buf_w2[(size_t)LLAY*DFFN*DDIM];

// ---------------- cp.async helpers ----------------
__device__ __forceinline__ void cpa16(void* s, const void* g) {
    unsigned sa = (unsigned)__cvta_generic_to_shared(s);
    asm volatile("cp.async.cg.shared.global [%0], [%1], 16;\n" :: "r"(sa), "l"(g));
}
__device__ __forceinline__ void cpa_commit() {
    asm volatile("cp.async.commit_group;\n");
}
template<int N>
__device__ __forceinline__ void cpa_wait() {
    asm volatile("cp.async.wait_group %0;\n" :: "n"(N));
}

// ---------------- fp32 -> fp16 conversion ----------------
__global__ __launch_bounds__(256) void f2h_kernel(const float* __restrict__ src,
                                                  __half* __restrict__ dst, int n)
{
    int stride = gridDim.x * blockDim.x * 4;
    for (int i = (blockIdx.x * blockDim.x + threadIdx.x) * 4; i < n; i += stride) {
        float4 v = *reinterpret_cast<const float4*>(src + i);
        __half2* d = reinterpret_cast<__half2*>(dst + i);
        d[0] = __floats2half2_rn(v.x, v.y);
        d[1] = __floats2half2_rn(v.z, v.w);
    }
}

// ---------------- LayerNorm (templated output type) ----------------
template<typename OutT>
__global__ __launch_bounds__(256) void ln_kernel(const float* __restrict__ X,
                                                 const float* __restrict__ gam,
                                                 const float* __restrict__ bet,
                                                 OutT* __restrict__ Y)
{
    int row = blockIdx.x;
    const float* x = X + (size_t)row * DDIM;
    int tid = threadIdx.x;
    float v0 = x[tid], v1 = x[tid + 256];

    __shared__ float red[8];
    __shared__ float stat[2];

    float s = v0 + v1;
    #pragma unroll
    for (int off = 16; off; off >>= 1) s += __shfl_xor_sync(0xffffffffu, s, off);
    if ((tid & 31) == 0) red[tid >> 5] = s;
    __syncthreads();
    if (tid < 8) {
        float t = red[tid];
        #pragma unroll
        for (int off = 4; off; off >>= 1) t += __shfl_xor_sync(0xffu, t, off);
        if (tid == 0) stat[0] = t * (1.0f / DDIM);
    }
    __syncthreads();
    float mean = stat[0];
    float d0 = v0 - mean, d1 = v1 - mean;
    float q = d0*d0 + d1*d1;
    #pragma unroll
    for (int off = 16; off; off >>= 1) q += __shfl_xor_sync(0xffffffffu, q, off);
    if ((tid & 31) == 0) red[tid >> 5] = q;
    __syncthreads();
    if (tid < 8) {
        float t = red[tid];
        #pragma unroll
        for (int off = 4; off; off >>= 1) t += __shfl_xor_sync(0xffu, t, off);
        if (tid == 0) stat[1] = rsqrtf(t * (1.0f / DDIM) + 1e-5f);
    }
    __syncthreads();
    float rs = stat[1];
    float y0 = d0 * rs * gam[tid]       + bet[tid];
    float y1 = d1 * rs * gam[tid + 256] + bet[tid + 256];
    if constexpr (sizeof(OutT) == 2) {
        Y[(size_t)row*DDIM + tid]       = __float2half_rn(y0);
        Y[(size_t)row*DDIM + tid + 256] = __float2half_rn(y1);
    } else {
        Y[(size_t)row*DDIM + tid]       = y0;
        Y[(size_t)row*DDIM + tid + 256] = y1;
    }
}

// ---------------- neighbor-list builder + bad-list compaction ----------------
__global__ __launch_bounds__(256) void nbr_build_kernel(const float* __restrict__ xy,
                                                        const int* __restrict__ alive,
                                                        const int* __restrict__ species,
                                                        int* __restrict__ nbr,
                                                        int* __restrict__ cnt,
                                                        int* __restrict__ bad,
                                                        int* __restrict__ nbad)
{
    int b = blockIdx.y;
    int q = blockIdx.x * 8 + (threadIdx.x >> 5);
    int lane = threadIdx.x & 31;
    float xq = xy[(b*NN+q)*2], yq = xy[(b*NN+q)*2+1];
    int sq = species[b*NN+q];
    bool qa = sq < 2, qp = sq == 2;
    size_t base = (size_t)(b*NN + q) * CAP;
    int c = 0;
    for (int k0 = 0; k0 < NN; k0 += 32) {
        int k = k0 + lane;
        float xk = xy[(b*NN+k)*2], yk = xy[(b*NN+k)*2+1];
        bool un = alive[b*NN+k] != 0;
        float dx = __fadd_rn(xq, -xk), dy = __fadd_rn(yq, -yk);
        float d2 = __fadd_rn(__fmul_rn(dx,dx), __fmul_rn(dy,dy));
        if (d2 > 100.0f) un = false;
        int sk = species[b*NN+k];
        bool ka = sk < 2, kp = sk == 2;
        if ((qa && kp) || (qp && ka)) un = false;
        unsigned bal = __ballot_sync(0xffffffffu, un);
        int pos = c + __popc(bal & ((1u << lane) - 1u));
        if (un && pos < CAP) nbr[base + pos] = k;
        c += __popc(bal);
    }
    if (lane == 0) {
        cnt[b*NN + q] = (c > CAP) ? CAP : c;
        if (c == 0) {
            int p = atomicAdd(&nbad[b], 1);
            bad[b*NN + p] = q;
        }
    }
}

// ---------------- sparse gather attention: warp per (b,h,q), register-resident ----------------
__global__ __launch_bounds__(256) void attn_sparse_kernel(const __half* __restrict__ Qh,
                                                          const __half* __restrict__ Kh,
                                                          const __half* __restrict__ Vh,
                                                          const int* __restrict__ nbr,
                                                          const int* __restrict__ cnt,
                                                          __half* __restrict__ O)
{
    int b = blockIdx.z, h = blockIdx.y;
    int w = threadIdx.x >> 5, lane = threadIdx.x & 31;
    int q = blockIdx.x * 8 + w;

    __shared__ float Qs[8][DHH];

    size_t qrow = (size_t)(b*NN + q);
    int c = cnt[qrow];

    // Q row: 32 half2 loads cover 64 dims
    {
        __half2 qh = reinterpret_cast<const __half2*>(&Qh[qrow*DDIM + h*DHH])[lane];
        float2 qf = __half22float2(qh);
        Qs[w][2*lane]   = qf.x;
        Qs[w][2*lane+1] = qf.y;
    }
    __syncwarp();

    float s_l[NSLOT];
    int   id_l[NSLOT];
    float mloc = -3.0e38f;

    #pragma unroll
    for (int slot = 0; slot < NSLOT; slot++) {
        int i = slot*32 + lane;
        s_l[slot] = -3.0e38f; id_l[slot] = 0;
        if (i < c) {
            int idx = nbr[qrow*CAP + i];
            id_l[slot] = idx;
            const uint4* kp = reinterpret_cast<const uint4*>(&Kh[((size_t)(b*NN+idx))*DDIM + h*DHH]);
            float s = 0.f;
            #pragma unroll
            for (int t = 0; t < 8; t++) {
                uint4 u = kp[t];
                float2 f0 = __half22float2(*reinterpret_cast<__half2*>(&u.x));
                float2 f1 = __half22float2(*reinterpret_cast<__half2*>(&u.y));
                float2 f2 = __half22float2(*reinterpret_cast<__half2*>(&u.z));
                float2 f3 = __half22float2(*reinterpret_cast<__half2*>(&u.w));
                const float* qq = &Qs[w][t*8];
                s += qq[0]*f0.x + qq[1]*f0.y + qq[2]*f1.x + qq[3]*f1.y
                   + qq[4]*f2.x + qq[5]*f2.y + qq[6]*f3.x + qq[7]*f3.y;
            }
            s *= 0.125f;
            s_l[slot] = s;
            mloc = fmaxf(mloc, s);
        }
    }
    #pragma unroll
    for (int off = 16; off; off >>= 1) mloc = fmaxf(mloc, __shfl_xor_sync(0xffffffffu, mloc, off));

    float lsum = 0.f;
    #pragma unroll
    for (int slot = 0; slot < NSLOT; slot++) {
        if (slot*32 + lane < c) {
            float p = expf(s_l[slot] - mloc);
            s_l[slot] = p;
            lsum += p;
        }
    }
    #pragma unroll
    for (int off = 16; off; off >>= 1) lsum += __shfl_xor_sync(0xffffffffu, lsum, off);

    // phase 3: lane owns dims (2*lane, 2*lane+1); weights broadcast via shfl
    float oa = 0.f, ob = 0.f;
    #pragma unroll
    for (int slot = 0; slot < NSLOT; slot++) {
        int base = slot*32;
        if (base >= c) break;
        float wmine = s_l[slot];
        int   imine = id_l[slot];
        int nrem = c - base; if (nrem > 32) nrem = 32;
        for (int src = 0; src < nrem; src++) {
            float wj = __shfl_sync(0xffffffffu, wmine, src);
            int   ij = __shfl_sync(0xffffffffu, imine, src);
            __half2 v = reinterpret_cast<const __half2*>(&Vh[((size_t)(b*NN+ij))*DDIM + h*DHH])[lane];
            float2 vf = __half22float2(v);
            oa += wj*vf.x;
            ob += wj*vf.y;
        }
    }

    float inv = (c > 0) ? 1.0f / lsum : 0.f;
    reinterpret_cast<__half2*>(&O[qrow*DDIM + h*DHH])[lane] =
        __floats2half2_rn(oa * inv, ob * inv);
}

// ---------------- fallback for zero-neighbor rows ----------------
__global__ __launch_bounds__(256) void attn_fallback(const __half* __restrict__ Qh,
                                                     const __half* __restrict__ Kh,
                                                     const __half* __restrict__ Vh,
                                                     const float* __restrict__ xy,
                                                     const int* __restrict__ alive,
                                                     const int* __restrict__ species,
                                                     const int* __restrict__ bad,
                                                     const int* __restrict__ nbad,
                                                     __half* __restrict__ O)
{
    int b = blockIdx.y;
    int nb = nbad[b];
    int tid = threadIdx.x;
    int w = tid >> 5, lane = tid & 31;

    __shared__ float sc[NN];
    __shared__ float bs[NN];
    __shared__ float qs[DHH];
    __shared__ float vacc[4][DHH];
    __shared__ float red[8];
    __shared__ float stat[2];

    for (int it = blockIdx.x; it < nb; it += gridDim.x) {
        int q = bad[b*NN + it];
        float xq = xy[(b*NN+q)*2], yq = xy[(b*NN+q)*2+1];
        int sq = species[b*NN+q];
        bool qa = sq < 2, qp = sq == 2;

        for (int k = tid; k < NN; k += 256) {
            float xk = xy[(b*NN+k)*2], yk = xy[(b*NN+k)*2+1];
            float bias = (alive[b*NN+k] == 0) ? NEGINF : 0.f;
            float dx = __fadd_rn(xq, -xk), dy = __fadd_rn(yq, -yk);
            float d2 = __fadd_rn(__fmul_rn(dx,dx), __fmul_rn(dy,dy));
            if (d2 > 100.0f) bias += NEGINF;
            int sk = species[b*NN+k];
            bool ka = sk < 2, kp = sk == 2;
            if ((qa && kp) || (qp && ka)) bias += NEGINF;
            bs[k] = bias;
        }
        __syncthreads();

        for (int h = 0; h < HH; h++) {
            if (tid < DHH) qs[tid] = __half2float(Qh[((size_t)(b*NN+q))*DDIM + h*DHH + tid]);
            __syncthreads();

            // warp-per-key: lane covers dims (2*lane, 2*lane+1) via half2
            for (int k = w; k < NN; k += 8) {
                __half2 kh = reinterpret_cast<const __half2*>(&Kh[((size_t)(b*NN+k))*DDIM + h*DHH])[lane];
                float2 kf = __half22float2(kh);
                float p = qs[2*lane]*kf.x + qs[2*lane+1]*kf.y;
                #pragma unroll
                for (int off = 16; off; off >>= 1) p += __shfl_xor_sync(0xffffffffu, p, off);
                if (lane == 0) sc[k] = p * 0.125f + bs[k];
            }
            __syncthreads();

            float mloc = -3.0e38f;
            for (int k = tid; k < NN; k += 256) mloc = fmaxf(mloc, sc[k]);
            #pragma unroll
            for (int off = 16; off; off >>= 1) mloc = fmaxf(mloc, __shfl_xor_sync(0xffffffffu, mloc, off));
            if ((tid & 31) == 0) red[tid >> 5] = mloc;
            __syncthreads();
            if (tid < 8) {
                float t = red[tid];
                #pragma unroll
                for (int off = 4; off; off >>= 1) t = fmaxf(t, __shfl_xor_sync(0xffu, t, off));
                if (tid == 0) stat[0] = t;
            }
            __syncthreads();
            float m = stat[0];
            float ls = 0.f;
            for (int k = tid; k < NN; k += 256) {
                float p = expf(sc[k] - m);
                sc[k] = p;
                ls += p;
            }
            #pragma unroll
            for (int off = 16; off; off >>= 1) ls += __shfl_xor_sync(0xffffffffu, ls, off);
            if ((tid & 31) == 0) red[tid >> 5] = ls;
            __syncthreads();
            if (tid < 8) {
                float t = red[tid];
                #pragma unroll
                for (int off = 4; off; off >>= 1) t += __shfl_xor_sync(0xffu, t, off);
                if (tid == 0) stat[1] = t;
            }
            __syncthreads();
            float inv = 1.0f / stat[1];

            int cch = tid >> 6, d = tid & 63;
            float a = 0.f;
            int k0 = cch * 256;
            for (int k = k0; k < k0 + 256; k++)
                a += sc[k] * __half2float(Vh[((size_t)(b*NN+k))*DDIM + h*DHH + d]);
            vacc[cch][d] = a;
            __syncthreads();
            if (tid < DHH) {
                float o = vacc[0][tid] + vacc[1][tid] + vacc[2][tid] + vacc[3][tid];
                O[((size_t)(b*NN+q))*DDIM + h*DHH + tid] = __float2half_rn(o * inv);
            }
            __syncthreads();
        }
    }
}

// ---------------- fp16 GEMM: BM=128 BN=64 BK=64, cp.async 3-stage ----------------
#define GBM 128
#define GBN 64
#define GBK 64
#define ALD 72                       // 64 + 8 pad halves (144 B rows)
#define BLD 72
#define A_STG_BYTES (GBM*ALD*2)      // 18432
#define B_STG_BYTES (GBK*BLD*2)      // 9216
#define STG_BYTES (A_STG_BYTES + B_STG_BYTES)   // 27648
#define GEMM_SMEM_BYTES (3 * STG_BYTES)         // 82944

__device__ __forceinline__ float gelu_exact(float x) {
    return 0.5f * x * (1.0f + erff(x * 0.70710678118654752440f));
}

__device__ __forceinline__ void gemm_issue(const __half* __restrict__ A,
                                           const __half* __restrict__ W,
                                           int K, int Nc, int row0, int col0,
                                           int kt, char* stg, int tid)
{
    int k0 = kt * GBK;
    __half* As = reinterpret_cast<__half*>(stg);
    __half* Bs = reinterpret_cast<__half*>(stg + A_STG_BYTES);
    // A tile 128x64 halves: 1024 16B-chunks, 4 per thread
    #pragma unroll
    for (int i = 0; i < 4; i++) {
        int f = i * 256 + tid;
        int r = f >> 3, seg = (f & 7) * 8;
        cpa16(&As[r * ALD + seg], &A[(size_t)(row0 + r) * K + k0 + seg]);
    }
    // B tile 64x64 halves: 512 16B-chunks, 2 per thread
    #pragma unroll
    for (int i = 0; i < 2; i++) {
        int f = i * 256 + tid;
        int r = f >> 3, seg = (f & 7) * 8;
        cpa16(&Bs[r * BLD + seg], &W[(size_t)(k0 + r) * Nc + col0 + seg]);
    }
    cpa_commit();
}

template<typename OutT>
__device__ __forceinline__ void gemm_core(const __half* __restrict__ A,
                                          const __half* __restrict__ W,
                                          const float* __restrict__ bias,
                                          const float* __restrict__ resid,
                                          OutT* __restrict__ C,
                                          int K, int Nc, int act,
                                          int row0, int col0, char* smem)
{
    int tid  = threadIdx.x;
    int warp = tid >> 5;
    int lane = tid & 31;
    int wm = warp >> 1;
    int wn = warp & 1;

    wmma::fragment<wmma::accumulator, 16,16,16, float> acc[2][2];
    #pragma unroll
    for (int mi = 0; mi < 2; mi++)
        #pragma unroll
        for (int ni = 0; ni < 2; ni++) wmma::fill_fragment(acc[mi][ni], 0.f);

    int niter = K / GBK;
    gemm_issue(A, W, K, Nc, row0, col0, 0, smem, tid);
    gemm_issue(A, W, K, Nc, row0, col0, 1, smem + STG_BYTES, tid);

    for (int kt = 0; kt < niter; kt++) {
        if (kt < niter - 1) cpa_wait<1>(); else cpa_wait<0>();
        __syncthreads();

        char* st = smem + (kt % 3) * STG_BYTES;
        const __half* Ac = reinterpret_cast<const __half*>(st);
        const __half* Bc = reinterpret_cast<const __half*>(st + A_STG_BYTES);
        #pragma unroll
        for (int kk = 0; kk < GBK; kk += 16) {
            wmma::fragment<wmma::matrix_a, 16,16,16, __half, wmma::row_major> af[2];
            wmma::fragment<wmma::matrix_b, 16,16,16, __half, wmma::row_major> bf[2];
            #pragma unroll
            for (int mi = 0; mi < 2; mi++)
                wmma::load_matrix_sync(af[mi], &Ac[(wm*32 + mi*16) * ALD + kk], ALD);
            #pragma unroll
            for (int ni = 0; ni < 2; ni++)
                wmma::load_matrix_sync(bf[ni], &Bc[kk * BLD + wn*32 + ni*16], BLD);
            #pragma unroll
            for (int mi = 0; mi < 2; mi++)
                #pragma unroll
                for (int ni = 0; ni < 2; ni++)
                    wmma::mma_sync(acc[mi][ni], af[mi], bf[ni], acc[mi][ni]);
        }

        if (kt + 2 < niter)
            gemm_issue(A, W, K, Nc, row0, col0, kt + 2, smem + ((kt + 2) % 3) * STG_BYTES, tid);
    }
    __syncthreads();

    float* st = reinterpret_cast<float*>(smem) + warp * 256;
    #pragma unroll
    for (int mi = 0; mi < 2; mi++) {
        #pragma unroll
        for (int ni = 0; ni < 2; ni++) {
            wmma::store_matrix_sync(st, acc[mi][ni], 16, wmma::mem_row_major);
            __syncwarp();
            int gr0 = row0 + wm*32 + mi*16;
            int gc0 = col0 + wn*32 + ni*16;
            #pragma unroll
            for (int i = 0; i < 8; i++) {
                int idx = i*32 + lane;
                int r = idx >> 4, cc = idx & 15;
                float v = st[idx];
                if (bias)  v += bias[gc0 + cc];
                if (act)   v  = gelu_exact(v);
                if (resid) v += resid[(size_t)(gr0 + r) * Nc + gc0 + cc];
                if constexpr (sizeof(OutT) == 2)
                    C[(size_t)(gr0 + r) * Nc + gc0 + cc] = __float2half_rn(v);
                else
                    C[(size_t)(gr0 + r) * Nc + gc0 + cc] = v;
            }
            __syncwarp();
        }
    }
}

__global__ __launch_bounds__(256, 2) void gemm_f32(const __half* __restrict__ A,
                                                   const __half* __restrict__ W,
                                                   const float* __restrict__ bias,
                                                   const float* __restrict__ resid,
                                                   float* __restrict__ C,
                                                   int K, int Nc, int act)
{
    extern __shared__ char smem[];
    gemm_core<float>(A, W, bias, resid, C, K, Nc, act,
                     blockIdx.y * GBM, blockIdx.x * GBN, smem);
}

__global__ __launch_bounds__(256, 2) void gemm_f16(const __half* __restrict__ A,
                                                   const __half* __restrict__ W,
                                                   const float* __restrict__ bias,
                                                   const float* __restrict__ resid,
                                                   __half* __restrict__ C,
                                                   int K, int Nc, int act)
{
    extern __shared__ char smem[];
    gemm_core<__half>(A, W, bias, resid, C, K, Nc, act,
                      blockIdx.y * GBM, blockIdx.x * GBN, smem);
}

__global__ __launch_bounds__(256, 2) void gemm_qkv(const __half* __restrict__ A,
                                                   const __half* __restrict__ Wq,
                                                   const __half* __restrict__ Wk,
                                                   const __half* __restrict__ Wv,
                                                   __half* __restrict__ Cq,
                                                   __half* __restrict__ Ck,
                                                   __half* __restrict__ Cv)
{
    extern __shared__ char smem[];
    int z = blockIdx.z;
    const __half* W = (z == 0) ? Wq : (z == 1) ? Wk : Wv;
    __half*       C = (z == 0) ? Cq : (z == 1) ? Ck : Cv;
    gemm_core<__half>(A, W, nullptr, nullptr, C, DDIM, DDIM, 0,
                      blockIdx.y * GBM, blockIdx.x * GBN, smem);
}

// ---------------- host orchestration ----------------
extern "C" void kernel_launch(void* const* d_in, const int* in_sizes, int n_in,
                              void* d_out, int out_size)
{
    (void)in_sizes; (void)n_in; (void)out_size;
    const float* tokens  = (const float*)d_in[0];
    const float* xy      = (const float*)d_in[1];
    const float* Wq      = (const float*)d_in[2];
    const float* Wk      = (const float*)d_in[3];
    const float* Wv      = (const float*)d_in[4];
    const float* Wo      = (const float*)d_in[5];
    const float* bo      = (const float*)d_in[6];
    const float* W1      = (const float*)d_in[7];
    const float* b1      = (const float*)d_in[8];
    const float* W2      = (const float*)d_in[9];
    const float* b2      = (const float*)d_in[10];
    const float* g1      = (const float*)d_in[11];
    const float* be1     = (const float*)d_in[12];
    const float* g2      = (const float*)d_in[13];
    const float* be2     = (const float*)d_in[14];
    const float* gf      = (const float*)d_in[15];
    const float* bf      = (const float*)d_in[16];
    const int*   alive   = (const int*)d_in[17];
    const int*   species = (const int*)d_in[18];

    __half *p_h, *p_q, *p_k, *p_v, *p_o, *p_ff;
    __half *p_wq, *p_wk, *p_wv, *p_wo, *p_w1, *p_w2;
    float *p_x;
    int *p_nbr, *p_cnt, *p_bad, *p_nbad;
    cudaGetSymbolAddress((void**)&p_h,  buf_h);
    cudaGetSymbolAddress((void**)&p_q,  buf_q);
    cudaGetSymbolAddress((void**)&p_k,  buf_k);
    cudaGetSymbolAddress((void**)&p_v,  buf_v);
    cudaGetSymbolAddress((void**)&p_o,  buf_o);
    cudaGetSymbolAddress((void**)&p_x,  buf_x);
    cudaGetSymbolAddress((void**)&p_ff, buf_ff);
    cudaGetSymbolAddress((void**)&p_nbr, buf_nbr);
    cudaGetSymbolAddress((void**)&p_cnt, buf_cnt);
    cudaGetSymbolAddress((void**)&p_bad, buf_bad);
    cudaGetSymbolAddress((void**)&p_nbad, buf_nbad);
    cudaGetSymbolAddress((void**)&p_wq, buf_wq);
    cudaGetSymbolAddress((void**)&p_wk, buf_wk);
    cudaGetSymbolAddress((void**)&p_wv, buf_wv);
    cudaGetSymbolAddress((void**)&p_wo, buf_wo);
    cudaGetSymbolAddress((void**)&p_w1, buf_w1);
    cudaGetSymbolAddress((void**)&p_w2, buf_w2);

    static int smem_set = 0;
    if (!smem_set) {
        cudaFuncSetAttribute(gemm_f32, cudaFuncAttributeMaxDynamicSharedMemorySize, GEMM_SMEM_BYTES);
        cudaFuncSetAttribute(gemm_f16, cudaFuncAttributeMaxDynamicSharedMemorySize, GEMM_SMEM_BYTES);
        cudaFuncSetAttribute(gemm_qkv, cudaFuncAttributeMaxDynamicSharedMemorySize, GEMM_SMEM_BYTES);
        smem_set = 1;
    }

    const int M = MROWS;
    const int NDD = LLAY * DDIM * DDIM;
    const int NDF = LLAY * DDIM * DFFN;

    f2h_kernel<<<512, 256>>>(Wq, p_wq, NDD);
    f2h_kernel<<<512, 256>>>(Wk, p_wk, NDD);
    f2h_kernel<<<512, 256>>>(Wv, p_wv, NDD);
    f2h_kernel<<<512, 256>>>(Wo, p_wo, NDD);
    f2h_kernel<<<1024, 256>>>(W1, p_w1, NDF);
    f2h_kernel<<<1024, 256>>>(W2, p_w2, NDF);

    dim3 gD(DDIM / GBN, M / GBM);
    dim3 gQKV(DDIM / GBN, M / GBM, 3);
    dim3 gF(DFFN / GBN, M / GBM);
    dim3 attnG(NN / 8, HH, BB);
    dim3 fbG(32, BB);

    cudaMemsetAsync(p_nbad, 0, BB * sizeof(int));
    nbr_build_kernel<<<dim3(NN/8, BB), 256>>>(xy, alive, species, p_nbr, p_cnt, p_bad, p_nbad);

    for (int l = 0; l < LLAY; l++) {
        const float* xsrc = (l == 0) ? tokens : p_x;
        size_t offD = (size_t)l * DDIM * DDIM;
        size_t offF = (size_t)l * DDIM * DFFN;

        ln_kernel<__half><<<M, 256>>>(xsrc, g1 + l * DDIM, be1 + l * DDIM, p_h);

        gemm_qkv<<<gQKV, 256, GEMM_SMEM_BYTES>>>(p_h, p_wq + offD, p_wk + offD, p_wv + offD,
                                                 p_q, p_k, p_v);

        attn_sparse_kernel<<<attnG, 256>>>(p_q, p_k, p_v, p_nbr, p_cnt, p_o);
        attn_fallback<<<fbG, 256>>>(p_q, p_k, p_v, xy, alive, species, p_bad, p_nbad, p_o);

        gemm_f32<<<gD, 256, GEMM_SMEM_BYTES>>>(p_o, p_wo + offD, bo + l * DDIM, xsrc, p_x,
                                               DDIM, DDIM, 0);

        ln_kernel<__half><<<M, 256>>>(p_x, g2 + l * DDIM, be2 + l * DDIM, p_h);

        gemm_f16<<<gF, 256, GEMM_SMEM_BYTES>>>(p_h, p_w1 + offF, b1 + l * DFFN, nullptr, p_ff,
                                               DDIM, DFFN, 1);
        gemm_f32<<<gD, 256, GEMM_SMEM_BYTES>>>(p_ff, p_w2 + offF, b2 + l * DDIM, p_x, p_x,
                                               DFFN, DDIM, 0);
    }

    ln_kernel<float><<<M, 256>>>(p_x, gf, bf, (float*)d_out);
}